// round 14
// baseline (speedup 1.0000x reference)
#include <cuda_runtime.h>
#include <cuda_bf16.h>
#include <math.h>
#include <stdint.h>

// ---------------------------------------------------------------------------
// CapsNet forward, B=32. Dominant cost: FC 102400->9216 (3.77 GB weights).
// R14: mma.sync bf16 hi/lo FC with prefetch-distance-2 register pipeline
// (R13 exposed ~600cyc of weight-LDG latency every chunk: nothing saturated,
// issue 29.5%) and 1-instr bf16x2 packing.
// ---------------------------------------------------------------------------

#define FC_M      9216
#define FC_K      102400
#define FC_SPLITK 8
#define FC_KSEG   12800     // FC_K / FC_SPLITK
#define FC_NCH    800       // FC_KSEG / 16
#define AST       12        // smem words per bf16 row (48B: 16 bf16 + pad)

// output section offsets (concatenated tuple, fp32)
#define OFF_LOGITS 0
#define OFF_RECON  320
#define OFF_PRIM   25408
#define OFF_DIGIT  320320
#define OFF_C      325440
#define OFF_B      694080

// ---------------- device scratch (static; allocations are forbidden) -------
__device__ __align__(16) float g_xT[784 * 32];
__device__ __align__(16) float g_flatT[FC_K * 32];                 // 13.1 MB
__device__ __align__(16) __nv_bfloat16 g_actH[32 * FC_K];          //  6.6 MB
__device__ __align__(16) __nv_bfloat16 g_actL[32 * FC_K];          //  6.6 MB
__device__ __align__(16) float g_Cpart[FC_SPLITK * FC_M * 32];     //  9.4 MB
__device__ __align__(16) float g_capsT[FC_M * 32];
__device__ __align__(16) float g_uhatT[10 * 1152 * 16 * 32];       // 23.6 MB
__device__ __align__(16) float g_bT[10 * 1152 * 32];
__device__ __align__(16) float g_cT[10 * 1152 * 32];
__device__ __align__(16) float g_spart[10 * 36 * 16 * 32];
__device__ __align__(16) float g_v[10 * 32 * 16];
__device__ __align__(16) float g_masked[160 * 32];
__device__ __align__(16) float g_d1[512 * 32];
__device__ __align__(16) float g_d2[1024 * 32];

// ---------------- helpers ---------------------------------------------------
__device__ __forceinline__ void split_bf2(float a, float b,
                                          uint32_t& hi, uint32_t& lo) {
    __nv_bfloat162 h = __floats2bfloat162_rn(a, b);      // 1 instr (bf16x2)
    float2 hf = __bfloat1622float2(h);
    __nv_bfloat162 l = __floats2bfloat162_rn(a - hf.x, b - hf.y);
    hi = *reinterpret_cast<uint32_t*>(&h);
    lo = *reinterpret_cast<uint32_t*>(&l);
}
// mma.sync m16n8k16 row.col f32.bf16.bf16.f32 (arch-generic, sm_80+)
__device__ __forceinline__ void mma16816(float* c,
                                         uint32_t a0, uint32_t a1,
                                         uint32_t a2, uint32_t a3,
                                         uint32_t b0, uint32_t b1) {
    asm volatile(
        "mma.sync.aligned.m16n8k16.row.col.f32.bf16.bf16.f32 "
        "{%0,%1,%2,%3}, {%4,%5,%6,%7}, {%8,%9}, {%0,%1,%2,%3};"
        : "+f"(c[0]), "+f"(c[1]), "+f"(c[2]), "+f"(c[3])
        : "r"(a0), "r"(a1), "r"(a2), "r"(a3), "r"(b0), "r"(b1));
}

// ---------------------------------------------------------------------------
// 0) x [32][784] -> xT [784][32]
// ---------------------------------------------------------------------------
__global__ void xT_kernel(const float* __restrict__ x) {
    int idx = blockIdx.x * 256 + threadIdx.x;
    if (idx < 784 * 32) {
        int b = idx / 784;
        int pix = idx - b * 784;
        g_xT[pix * 32 + b] = x[idx];
    }
}

// ---------------------------------------------------------------------------
// 1) conv 9x9 VALID + bias + relu -> flatT[k][b]
// ---------------------------------------------------------------------------
__global__ void conv_kernel(const float* __restrict__ cw,
                            const float* __restrict__ cb) {
    int idx = blockIdx.x * 256 + threadIdx.x;
    int b = idx & 31;
    int k = idx >> 5;
    int oc = k / 400;
    int pos = k - oc * 400;
    int oh = pos / 20;
    int ow = pos - oh * 20;
    float acc = cb[oc];
    const float* wp = cw + oc * 81;
#pragma unroll
    for (int r = 0; r < 9; ++r) {
#pragma unroll
        for (int cc = 0; cc < 9; ++cc) {
            acc = fmaf(g_xT[((oh + r) * 28 + ow + cc) * 32 + b], wp[r * 9 + cc], acc);
        }
    }
    g_flatT[(size_t)k * 32 + b] = fmaxf(acc, 0.f);
}

// ---------------------------------------------------------------------------
// 1b) act hi/lo bf16 split: flatT[k][b] -> actH/actL[b][k]
// ---------------------------------------------------------------------------
__global__ void actcvt_kernel() {
    int idx = blockIdx.x * 256 + threadIdx.x;    // 3,276,800
    int b = idx / FC_K;
    int k = idx - b * FC_K;
    float f = g_flatT[(size_t)k * 32 + b];
    __nv_bfloat16 h = __float2bfloat16_rn(f);
    g_actH[(size_t)b * FC_K + k] = h;
    g_actL[(size_t)b * FC_K + k] = __float2bfloat16_rn(f - __bfloat162float(h));
}

// ---------------------------------------------------------------------------
// 2) FC via mma.sync bf16 hi/lo: Cpart[sk][m][b] = sum_k W[m][k]*act[b][k]
//    Block 256 = 8 warps, BM=128 (m16/warp), N=32 (4 n8), BK=16.
//    Prefetch distance 2: at iter c load chunk c+2 (reg slot c&1), compute
//    chunk c (smem), stage chunk c+1 from reg slot (c+1)&1 (data arrived a
//    full iteration ago -> no exposed LDG scoreboard).
// ---------------------------------------------------------------------------
__global__ void __launch_bounds__(256, 2)
fc_hmma_kernel(const float* __restrict__ fcw) {
    __shared__ __align__(16) uint32_t aH[2][128 * AST];   // 12 KB
    __shared__ __align__(16) uint32_t aL[2][128 * AST];   // 12 KB
    __shared__ __align__(16) uint32_t bHs[2][32 * AST];   //  3 KB
    __shared__ __align__(16) uint32_t bLs[2][32 * AST];   //  3 KB

    const int t = threadIdx.x;
    const int mbase = blockIdx.x * 128;
    const long long kbase = (long long)blockIdx.y * FC_KSEG;

    // A loader: rows lr, lr+64; float4 col group lc (floats lc*4..lc*4+3)
    const int lr = t >> 2;                   // 0..63
    const int lc = t & 3;                    // 0..3
    const float* wp0 = fcw + (size_t)(mbase + lr) * FC_K + kbase + lc * 4;
    const float* wp1 = wp0 + (size_t)64 * FC_K;
    // B loader: threads 0..127 (t<64 -> hi, else lo); n=(t&63)>>1, half=t&1
    const int bn = (t & 63) >> 1;
    const int bh2 = t & 1;
    const __nv_bfloat16* bsrc =
        (t < 64 ? g_actH : g_actL) + (size_t)bn * FC_K + kbase + bh2 * 8;

    // compute mapping
    const int w = t >> 5;                    // warp: rows w*16..w*16+15
    const int lane = t & 31;
    const int gr = lane >> 2;                // 0..7
    const int gc = lane & 3;                 // 0..3

    float acc[4][4];
#pragma unroll
    for (int j = 0; j < 4; ++j)
#pragma unroll
        for (int q = 0; q < 4; ++q) acc[j][q] = 0.f;

    float4 a0[2], a1[2];
    uint4 bv[2];

    // staging helper (lambda-like macro): stage chunk from reg slot S into
    // smem buffer D
#define FC_STAGE_FROM(S, D)                                                  \
    {                                                                        \
        uint32_t h0, l0, h1, l1;                                             \
        split_bf2(a0[S].x, a0[S].y, h0, l0);                                 \
        split_bf2(a0[S].z, a0[S].w, h1, l1);                                 \
        int wd = lr * AST + lc * 2;                                          \
        *(uint2*)&aH[D][wd] = make_uint2(h0, h1);                            \
        *(uint2*)&aL[D][wd] = make_uint2(l0, l1);                            \
        split_bf2(a1[S].x, a1[S].y, h0, l0);                                 \
        split_bf2(a1[S].z, a1[S].w, h1, l1);                                 \
        wd = (lr + 64) * AST + lc * 2;                                       \
        *(uint2*)&aH[D][wd] = make_uint2(h0, h1);                            \
        *(uint2*)&aL[D][wd] = make_uint2(l0, l1);                            \
        if (t < 128) {                                                       \
            uint32_t* bt = (t < 64) ? bHs[D] : bLs[D];                       \
            *(uint4*)&bt[bn * AST + bh2 * 4] = bv[S];                        \
        }                                                                    \
    }

    // ---- prologue ----
    // chunk 0 -> slot 0, chunk 1 -> slot 1; stage chunk 0 (slot 0 then free)
    a0[0] = *(const float4*)(wp0);
    a1[0] = *(const float4*)(wp1);
    if (t < 128) bv[0] = *(const uint4*)bsrc;
    a0[1] = *(const float4*)(wp0 + 16);
    a1[1] = *(const float4*)(wp1 + 16);
    if (t < 128) bv[1] = *(const uint4*)(bsrc + 16);
    FC_STAGE_FROM(0, 0)
    __syncthreads();

#pragma unroll 1
    for (int c = 0; c < FC_NCH; ++c) {
        const int buf = c & 1;

        // load chunk c+2 into reg slot buf (its previous contents, chunk c,
        // were staged at iteration c-1)
        if (c + 2 < FC_NCH) {
            a0[buf] = *(const float4*)(wp0 + (size_t)(c + 2) * 16);
            a1[buf] = *(const float4*)(wp1 + (size_t)(c + 2) * 16);
            if (t < 128) bv[buf] = *(const uint4*)(bsrc + (size_t)(c + 2) * 16);
        }

        // ---- compute chunk c from smem[buf] ----
        {
            const int ab = w * 16 + gr;
            const uint32_t ah0 = aH[buf][ab * AST + gc];
            const uint32_t ah1 = aH[buf][(ab + 8) * AST + gc];
            const uint32_t ah2 = aH[buf][ab * AST + 4 + gc];
            const uint32_t ah3 = aH[buf][(ab + 8) * AST + 4 + gc];
            const uint32_t al0 = aL[buf][ab * AST + gc];
            const uint32_t al1 = aL[buf][(ab + 8) * AST + gc];
            const uint32_t al2 = aL[buf][ab * AST + 4 + gc];
            const uint32_t al3 = aL[buf][(ab + 8) * AST + 4 + gc];
#pragma unroll
            for (int j = 0; j < 4; ++j) {
                const int nb = (j * 8 + gr) * AST + gc;
                const uint32_t bh0 = bHs[buf][nb];
                const uint32_t bh1 = bHs[buf][nb + 4];
                const uint32_t bl0 = bLs[buf][nb];
                const uint32_t bl1 = bLs[buf][nb + 4];
                mma16816(acc[j], ah0, ah1, ah2, ah3, bh0, bh1);   // hi*hi
                mma16816(acc[j], ah0, ah1, ah2, ah3, bl0, bl1);   // hi*lo
                mma16816(acc[j], al0, al1, al2, al3, bh0, bh1);   // lo*hi
            }
        }

        // ---- stage chunk c+1 from reg slot buf^1 into smem[buf^1] ----
        if (c + 1 < FC_NCH) {
            const int nbuf = buf ^ 1;
            FC_STAGE_FROM(nbuf, nbuf)
        }
        __syncthreads();
    }

    // ---- epilogue: C[m][n] fragments -> g_Cpart ----
    const int m0 = mbase + w * 16 + gr;
#pragma unroll
    for (int j = 0; j < 4; ++j) {
        const int n0 = j * 8 + gc * 2;
        float* d0 = g_Cpart + ((size_t)blockIdx.y * FC_M + m0) * 32 + n0;
        float* d1 = d0 + (size_t)8 * 32;
        *(float2*)d0 = make_float2(acc[j][0], acc[j][1]);
        *(float2*)d1 = make_float2(acc[j][2], acc[j][3]);
    }
#undef FC_STAGE_FROM
}

// ---------------------------------------------------------------------------
// 3) reduce split-K + bias + squash -> primary caps output + capsT scratch
// ---------------------------------------------------------------------------
__global__ void caps_kernel(const float* __restrict__ fcb,
                            float* __restrict__ out) {
    int idx = blockIdx.x * 256 + threadIdx.x;   // 36864
    int b = idx & 31;
    int cap = idx >> 5;
    float pc[8];
    float n2 = 0.f;
#pragma unroll
    for (int d = 0; d < 8; ++d) {
        int m = cap * 8 + d;
        float v = fcb[m];
#pragma unroll
        for (int s = 0; s < FC_SPLITK; ++s)
            v += g_Cpart[((size_t)s * FC_M + m) * 32 + b];
        pc[d] = v;
        n2 += v * v;
    }
    float scale = n2 / (1.f + n2);
    float inv = 1.f / sqrtf(n2);
#pragma unroll
    for (int d = 0; d < 8; ++d) {
        float o = scale * (pc[d] * inv + 1e-8f);
        out[OFF_PRIM + (size_t)b * 9216 + cap * 8 + d] = o;
        g_capsT[(cap * 8 + d) * 32 + b] = o;
    }
}

// ---------------------------------------------------------------------------
// 4) u_hat[b,n,p,d] = sum_i W[0,n,p,d,i] * caps[b,p,i] -> g_uhatT[n][p][d][b]
// ---------------------------------------------------------------------------
__global__ void uhat_kernel(const float* __restrict__ W) {
    int idx = blockIdx.x * 256 + threadIdx.x;   // 368640
    int b = idx & 31;
    int r = idx >> 5;                            // n*1152 + p
    int p = r % 1152;
    float caps[8];
#pragma unroll
    for (int i = 0; i < 8; ++i) caps[i] = g_capsT[(p * 8 + i) * 32 + b];
    const float* Wp = W + (size_t)r * 128;       // warp-uniform broadcast
    float* up = g_uhatT + (size_t)r * 512 + b;
#pragma unroll
    for (int d = 0; d < 16; ++d) {
        float a = 0.f;
#pragma unroll
        for (int i = 0; i < 8; ++i) a = fmaf(Wp[d * 8 + i], caps[i], a);
        up[d * 32] = a;
    }
}

// ---------------------------------------------------------------------------
// 5a) partial s sums over p-chunks of 32: spart[n][ch][d][b]
// ---------------------------------------------------------------------------
__global__ void rout_sv_kernel(int uniformC) {
    int n = blockIdx.x / 36;
    int ch = blockIdx.x - n * 36;
    int t = threadIdx.x;                         // 512 = 16 d * 32 b
    int b = t & 31;
    int d = t >> 5;
    int rbase = n * 1152 + ch * 32;
    float a = 0.f;
#pragma unroll 8
    for (int pp = 0; pp < 32; ++pp) {
        size_t r = rbase + pp;
        float c = uniformC ? 0.1f : g_cT[r * 32 + b];
        a = fmaf(c, g_uhatT[(r * 16 + d) * 32 + b], a);
    }
    g_spart[(((size_t)n * 36 + ch) * 16 + d) * 32 + b] = a;
}

// 5b) reduce partials + squash -> v (and digit caps output when final)
__global__ void rout_squash_kernel(int final_, float* __restrict__ out) {
    int t = threadIdx.x;                         // 320
    int b = t & 31;
    int n = t >> 5;
    float s[16];
    float n2 = 0.f;
#pragma unroll
    for (int d = 0; d < 16; ++d) {
        float a = 0.f;
        for (int ch = 0; ch < 36; ++ch)
            a += g_spart[(((size_t)n * 36 + ch) * 16 + d) * 32 + b];
        s[d] = a;
        n2 += a * a;
    }
    float scale = n2 / (1.f + n2);
    float inv = 1.f / sqrtf(n2);
#pragma unroll
    for (int d = 0; d < 16; ++d) {
        float v = scale * (s[d] * inv + 1e-8f);
        g_v[(n * 32 + b) * 16 + d] = v;
        if (final_) out[OFF_DIGIT + (size_t)b * 160 + n * 16 + d] = v;
    }
}

// 5c) b += sum_d u_hat * v   (first iteration: b = uv, since b starts at 0)
__global__ void rout_update_kernel(int first) {
    int idx = blockIdx.x * 256 + threadIdx.x;   // 368640
    int b = idx & 31;
    int r = idx >> 5;
    int n = r / 1152;
    const float* up = g_uhatT + (size_t)r * 512 + b;
    const float* vp = g_v + ((size_t)n * 32 + b) * 16;
    float a = 0.f;
#pragma unroll
    for (int d = 0; d < 16; ++d) a = fmaf(up[d * 32], vp[d], a);
    size_t o = (size_t)r * 32 + b;
    g_bT[o] = (first ? 0.f : g_bT[o]) + a;
}

// 5d) c = softmax over n of b; optionally emit final c and b to output
__global__ void softmax_kernel(int write_out, float* __restrict__ out) {
    int idx = blockIdx.x * 256 + threadIdx.x;   // 36864
    int b = idx & 31;
    int p = idx >> 5;
    float bv[10];
    float m = -1e30f;
#pragma unroll
    for (int n = 0; n < 10; ++n) {
        bv[n] = g_bT[((size_t)n * 1152 + p) * 32 + b];
        m = fmaxf(m, bv[n]);
    }
    float e[10];
    float sum = 0.f;
#pragma unroll
    for (int n = 0; n < 10; ++n) {
        e[n] = expf(bv[n] - m);
        sum += e[n];
    }
    float invs = 1.f / sum;
#pragma unroll
    for (int n = 0; n < 10; ++n) {
        float c = e[n] * invs;
        g_cT[((size_t)n * 1152 + p) * 32 + b] = c;
        if (write_out) {
            out[OFF_C + ((size_t)b * 10 + n) * 1152 + p] = c;
            out[OFF_B + ((size_t)b * 10 + n) * 1152 + p] = bv[n];
        }
    }
}

// ---------------------------------------------------------------------------
// 6) logits = ||digit||, argmax (first max), masked -> g_masked[i][b]
// ---------------------------------------------------------------------------
__global__ void logits_kernel(float* __restrict__ out) {
    int b = threadIdx.x;                         // 32
    float dg[160];
    for (int i = 0; i < 160; ++i) dg[i] = out[OFF_DIGIT + (size_t)b * 160 + i];
    float best = -1.f;
    int am = 0;
    for (int n = 0; n < 10; ++n) {
        float n2 = 0.f;
        for (int d = 0; d < 16; ++d) {
            float v = dg[n * 16 + d];
            n2 += v * v;
        }
        float lg = sqrtf(n2);
        out[OFF_LOGITS + b * 10 + n] = lg;
        if (lg > best) { best = lg; am = n; }
    }
    for (int n = 0; n < 10; ++n)
        for (int d = 0; d < 16; ++d)
            g_masked[(n * 16 + d) * 32 + b] = (n == am) ? dg[n * 16 + d] : 0.f;
}

// ---------------------------------------------------------------------------
// 7) decoder MLP
// ---------------------------------------------------------------------------
__global__ void dec1_kernel(const float* __restrict__ Wt,
                            const float* __restrict__ bias) {
    int idx = blockIdx.x * 256 + threadIdx.x;   // 512*32
    int b = idx & 31, o = idx >> 5;
    const float* w = Wt + (size_t)o * 160;
    float a0 = 0.f, a1 = 0.f, a2 = 0.f, a3 = 0.f;
#pragma unroll 4
    for (int i = 0; i < 160; i += 4) {
        a0 = fmaf(w[i],     g_masked[(i)     * 32 + b], a0);
        a1 = fmaf(w[i + 1], g_masked[(i + 1) * 32 + b], a1);
        a2 = fmaf(w[i + 2], g_masked[(i + 2) * 32 + b], a2);
        a3 = fmaf(w[i + 3], g_masked[(i + 3) * 32 + b], a3);
    }
    g_d1[o * 32 + b] = fmaxf(bias[o] + ((a0 + a1) + (a2 + a3)), 0.f);
}

__global__ void dec2_kernel(const float* __restrict__ Wt,
                            const float* __restrict__ bias) {
    int idx = blockIdx.x * 256 + threadIdx.x;   // 1024*32
    int b = idx & 31, o = idx >> 5;
    const float* w = Wt + (size_t)o * 512;
    float a0 = 0.f, a1 = 0.f, a2 = 0.f, a3 = 0.f;
#pragma unroll 4
    for (int i = 0; i < 512; i += 4) {
        a0 = fmaf(w[i],     g_d1[(i)     * 32 + b], a0);
        a1 = fmaf(w[i + 1], g_d1[(i + 1) * 32 + b], a1);
        a2 = fmaf(w[i + 2], g_d1[(i + 2) * 32 + b], a2);
        a3 = fmaf(w[i + 3], g_d1[(i + 3) * 32 + b], a3);
    }
    g_d2[o * 32 + b] = fmaxf(bias[o] + ((a0 + a1) + (a2 + a3)), 0.f);
}

__global__ void dec3_kernel(const float* __restrict__ Wt,
                            const float* __restrict__ bias,
                            float* __restrict__ out) {
    int idx = blockIdx.x * 256 + threadIdx.x;   // 784*32
    int b = idx & 31, o = idx >> 5;
    const float* w = Wt + (size_t)o * 1024;
    float a0 = 0.f, a1 = 0.f, a2 = 0.f, a3 = 0.f;
#pragma unroll 4
    for (int i = 0; i < 1024; i += 4) {
        a0 = fmaf(w[i],     g_d2[(i)     * 32 + b], a0);
        a1 = fmaf(w[i + 1], g_d2[(i + 1) * 32 + b], a1);
        a2 = fmaf(w[i + 2], g_d2[(i + 2) * 32 + b], a2);
        a3 = fmaf(w[i + 3], g_d2[(i + 3) * 32 + b], a3);
    }
    float x = bias[o] + ((a0 + a1) + (a2 + a3));
    out[OFF_RECON + (size_t)b * 784 + o] = 1.f / (1.f + expf(-x));
}

// ---------------------------------------------------------------------------
// Resolve inputs by (unique) element count — order-independent binding.
// ---------------------------------------------------------------------------
static const float* by_size(void* const* d_in, const int* s, int n, int want) {
    for (int i = 0; i < n; ++i)
        if (s[i] == want) return (const float*)d_in[i];
    return nullptr;
}

extern "C" void kernel_launch(void* const* d_in, const int* in_sizes, int n_in,
                              void* d_out, int out_size) {
    const float* x   = by_size(d_in, in_sizes, n_in, 32 * 784);        // 25088
    const float* cw  = by_size(d_in, in_sizes, n_in, 256 * 81);        // 20736
    const float* cb  = by_size(d_in, in_sizes, n_in, 256);
    const float* fcw = by_size(d_in, in_sizes, n_in, 943718400);       // 9216*102400
    const float* fcb = by_size(d_in, in_sizes, n_in, 9216);
    const float* W   = by_size(d_in, in_sizes, n_in, 1474560);         // 10*1152*16*8
    const float* d1w = by_size(d_in, in_sizes, n_in, 512 * 160);       // 81920
    const float* d1b = by_size(d_in, in_sizes, n_in, 512);
    const float* d2w = by_size(d_in, in_sizes, n_in, 1024 * 512);      // 524288
    const float* d2b = by_size(d_in, in_sizes, n_in, 1024);
    const float* d3w = by_size(d_in, in_sizes, n_in, 784 * 1024);      // 802816
    const float* d3b = by_size(d_in, in_sizes, n_in, 784);
    float* out = (float*)d_out;

    xT_kernel<<<98, 256>>>(x);                           // launch 1
    conv_kernel<<<12800, 256>>>(cw, cb);                 // launch 2
    actcvt_kernel<<<12800, 256>>>();                     // launch 3
    fc_hmma_kernel<<<dim3(72, 8), 256>>>(fcw);           // launch 4 <- ncu slot
    caps_kernel<<<144, 256>>>(fcb, out);
    uhat_kernel<<<1440, 256>>>(W);

    // routing iteration 0 (c = softmax(0) = 0.1 uniform)
    rout_sv_kernel<<<360, 512>>>(1);
    rout_squash_kernel<<<1, 320>>>(0, out);
    rout_update_kernel<<<1440, 256>>>(1);
    // routing iteration 1
    softmax_kernel<<<144, 256>>>(0, out);
    rout_sv_kernel<<<360, 512>>>(0);
    rout_squash_kernel<<<1, 320>>>(0, out);
    rout_update_kernel<<<1440, 256>>>(0);
    // final pass (emit c, b, digit caps)
    softmax_kernel<<<144, 256>>>(1, out);
    rout_sv_kernel<<<360, 512>>>(0);
    rout_squash_kernel<<<1, 320>>>(1, out);

    logits_kernel<<<1, 32>>>(out);
    dec1_kernel<<<64, 256>>>(d1w, d1b);
    dec2_kernel<<<128, 256>>>(d2w, d2b);
    dec3_kernel<<<98, 256>>>(d3w, d3b, out);
}

// round 15
// speedup vs baseline: 1.8639x; 1.8639x over previous
#include <cuda_runtime.h>
#include <cuda_bf16.h>
#include <math.h>
#include <stdint.h>

// ---------------------------------------------------------------------------
// CapsNet forward, B=32. Dominant cost: FC 102400->9216 (3.77 GB weights).
// R15: mma.sync bf16 hi/lo FC; explicit 2-slot register pipeline (R14's
// dynamic-indexed slots spilled to local memory), BK=32 (half the syncs,
// 2x compute per phase), 4-sector warp LDG, conflict-free stride-20 smem.
// ---------------------------------------------------------------------------

#define FC_M      9216
#define FC_K      102400
#define FC_SPLITK 8
#define FC_KSEG   12800     // FC_K / FC_SPLITK
#define FC_NCH32  400       // FC_KSEG / 32
#define AST       20        // smem words per bf16 row (32 bf16 = 16w + pad 4)

// output section offsets (concatenated tuple, fp32)
#define OFF_LOGITS 0
#define OFF_RECON  320
#define OFF_PRIM   25408
#define OFF_DIGIT  320320
#define OFF_C      325440
#define OFF_B      694080

// ---------------- device scratch (static; allocations are forbidden) -------
__device__ __align__(16) float g_xT[784 * 32];
__device__ __align__(16) float g_flatT[FC_K * 32];                 // 13.1 MB
__device__ __align__(16) __nv_bfloat16 g_actH[32 * FC_K];          //  6.6 MB
__device__ __align__(16) __nv_bfloat16 g_actL[32 * FC_K];          //  6.6 MB
__device__ __align__(16) float g_Cpart[FC_SPLITK * FC_M * 32];     //  9.4 MB
__device__ __align__(16) float g_capsT[FC_M * 32];
__device__ __align__(16) float g_uhatT[10 * 1152 * 16 * 32];       // 23.6 MB
__device__ __align__(16) float g_bT[10 * 1152 * 32];
__device__ __align__(16) float g_cT[10 * 1152 * 32];
__device__ __align__(16) float g_spart[10 * 36 * 16 * 32];
__device__ __align__(16) float g_v[10 * 32 * 16];
__device__ __align__(16) float g_masked[160 * 32];
__device__ __align__(16) float g_d1[512 * 32];
__device__ __align__(16) float g_d2[1024 * 32];

// ---------------- helpers ---------------------------------------------------
__device__ __forceinline__ void split_bf2(float a, float b,
                                          uint32_t& hi, uint32_t& lo) {
    __nv_bfloat162 h = __floats2bfloat162_rn(a, b);      // 1 instr (bf16x2)
    float2 hf = __bfloat1622float2(h);
    __nv_bfloat162 l = __floats2bfloat162_rn(a - hf.x, b - hf.y);
    hi = *reinterpret_cast<uint32_t*>(&h);
    lo = *reinterpret_cast<uint32_t*>(&l);
}
// mma.sync m16n8k16 row.col f32.bf16.bf16.f32 (arch-generic, sm_80+)
__device__ __forceinline__ void mma16816(float* c,
                                         uint32_t a0, uint32_t a1,
                                         uint32_t a2, uint32_t a3,
                                         uint32_t b0, uint32_t b1) {
    asm volatile(
        "mma.sync.aligned.m16n8k16.row.col.f32.bf16.bf16.f32 "
        "{%0,%1,%2,%3}, {%4,%5,%6,%7}, {%8,%9}, {%0,%1,%2,%3};"
        : "+f"(c[0]), "+f"(c[1]), "+f"(c[2]), "+f"(c[3])
        : "r"(a0), "r"(a1), "r"(a2), "r"(a3), "r"(b0), "r"(b1));
}

// ---------------------------------------------------------------------------
// 0) x [32][784] -> xT [784][32]
// ---------------------------------------------------------------------------
__global__ void xT_kernel(const float* __restrict__ x) {
    int idx = blockIdx.x * 256 + threadIdx.x;
    if (idx < 784 * 32) {
        int b = idx / 784;
        int pix = idx - b * 784;
        g_xT[pix * 32 + b] = x[idx];
    }
}

// ---------------------------------------------------------------------------
// 1) conv 9x9 VALID + bias + relu -> flatT[k][b]
// ---------------------------------------------------------------------------
__global__ void conv_kernel(const float* __restrict__ cw,
                            const float* __restrict__ cb) {
    int idx = blockIdx.x * 256 + threadIdx.x;
    int b = idx & 31;
    int k = idx >> 5;
    int oc = k / 400;
    int pos = k - oc * 400;
    int oh = pos / 20;
    int ow = pos - oh * 20;
    float acc = cb[oc];
    const float* wp = cw + oc * 81;
#pragma unroll
    for (int r = 0; r < 9; ++r) {
#pragma unroll
        for (int cc = 0; cc < 9; ++cc) {
            acc = fmaf(g_xT[((oh + r) * 28 + ow + cc) * 32 + b], wp[r * 9 + cc], acc);
        }
    }
    g_flatT[(size_t)k * 32 + b] = fmaxf(acc, 0.f);
}

// ---------------------------------------------------------------------------
// 1b) act hi/lo bf16 split: flatT[k][b] -> actH/actL[b][k]
// ---------------------------------------------------------------------------
__global__ void actcvt_kernel() {
    int idx = blockIdx.x * 256 + threadIdx.x;    // 3,276,800
    int b = idx / FC_K;
    int k = idx - b * FC_K;
    float f = g_flatT[(size_t)k * 32 + b];
    __nv_bfloat16 h = __float2bfloat16_rn(f);
    g_actH[(size_t)b * FC_K + k] = h;
    g_actL[(size_t)b * FC_K + k] = __float2bfloat16_rn(f - __bfloat162float(h));
}

// ---------------------------------------------------------------------------
// 2) FC via mma.sync bf16 hi/lo: Cpart[sk][m][b] = sum_k W[m][k]*act[b][k]
//    Block 256 = 8 warps, BM=128 (m16/warp), N=32 (4 n8), BK=32 (2 k16).
//    Two named register slots (A/B); chunk loop unrolled x2 so prefetch
//    distance >= one full compute+stage phase and nothing spills.
// ---------------------------------------------------------------------------
__global__ void __launch_bounds__(256, 2)
fc_hmma_kernel(const float* __restrict__ fcw) {
    __shared__ __align__(16) uint32_t aH[2][128 * AST];   // 20 KB
    __shared__ __align__(16) uint32_t aL[2][128 * AST];   // 20 KB
    __shared__ __align__(16) uint32_t bHs[2][32 * AST];   //  5 KB
    __shared__ __align__(16) uint32_t bLs[2][32 * AST];   //  5 KB

    const int t = threadIdx.x;
    const int mbase = blockIdx.x * 128;
    const long long kbase = (long long)blockIdx.y * FC_KSEG;

    // A loader: rows lr+32j (j=0..3), float4 group lc within the 32-float row
    const int lr = t >> 3;                   // 0..31
    const int lc = t & 7;                    // 0..7
    const float* wrow = fcw + (size_t)(mbase + lr) * FC_K + kbase + lc * 4;
    const size_t wj = (size_t)32 * FC_K;
    // B loader: all 256 threads; t<128 -> hi, else lo; n=(t&127)>>2, kq=t&3
    const int bn = (t & 127) >> 2;           // 0..31
    const int kq = t & 3;                    // uint4 index (8 bf16 each)
    const __nv_bfloat16* bsrc =
        (t < 128 ? g_actH : g_actL) + (size_t)bn * FC_K + kbase + kq * 8;

    // compute mapping
    const int w = t >> 5;                    // warp: rows w*16..w*16+15
    const int lane = t & 31;
    const int gr = lane >> 2;                // 0..7
    const int gc = lane & 3;                 // 0..3

    float acc[4][4];
#pragma unroll
    for (int j = 0; j < 4; ++j)
#pragma unroll
        for (int q = 0; q < 4; ++q) acc[j][q] = 0.f;

    float4 wA[4], wB[4];
    uint4 bvA, bvB;

#define FC_LOAD(WS, BV, C)                                                   \
    {                                                                        \
        const float* p = wrow + (size_t)(C) * 32;                            \
        WS[0] = *(const float4*)(p);                                         \
        WS[1] = *(const float4*)(p + wj);                                    \
        WS[2] = *(const float4*)(p + 2 * wj);                                \
        WS[3] = *(const float4*)(p + 3 * wj);                                \
        BV = *(const uint4*)(bsrc + (size_t)(C) * 32);                       \
    }

#define FC_STAGE(WS, BV, D)                                                  \
    _Pragma("unroll")                                                        \
    for (int j = 0; j < 4; ++j) {                                            \
        uint32_t h0, l0, h1, l1;                                             \
        split_bf2(WS[j].x, WS[j].y, h0, l0);                                 \
        split_bf2(WS[j].z, WS[j].w, h1, l1);                                 \
        const int wd = (lr + 32 * j) * AST + lc * 2;                         \
        *(uint2*)&aH[D][wd] = make_uint2(h0, h1);                            \
        *(uint2*)&aL[D][wd] = make_uint2(l0, l1);                            \
    }                                                                        \
    {                                                                        \
        uint32_t* bt = (t < 128) ? bHs[D] : bLs[D];                          \
        *(uint4*)&bt[bn * AST + kq * 4] = BV;                                \
    }

#define FC_COMPUTE(D)                                                        \
    _Pragma("unroll")                                                        \
    for (int s = 0; s < 2; ++s) {                                            \
        const int ab = (w * 16 + gr) * AST + s * 8;                          \
        const uint32_t ah0 = aH[D][ab + gc];                                 \
        const uint32_t ah1 = aH[D][ab + 8 * AST + gc];                       \
        const uint32_t ah2 = aH[D][ab + 4 + gc];                             \
        const uint32_t ah3 = aH[D][ab + 8 * AST + 4 + gc];                   \
        const uint32_t al0 = aL[D][ab + gc];                                 \
        const uint32_t al1 = aL[D][ab + 8 * AST + gc];                       \
        const uint32_t al2 = aL[D][ab + 4 + gc];                             \
        const uint32_t al3 = aL[D][ab + 8 * AST + 4 + gc];                   \
        _Pragma("unroll")                                                    \
        for (int j = 0; j < 4; ++j) {                                        \
            const int nb = (j * 8 + gr) * AST + s * 8 + gc;                  \
            const uint32_t bh0 = bHs[D][nb];                                 \
            const uint32_t bh1 = bHs[D][nb + 4];                             \
            const uint32_t bl0 = bLs[D][nb];                                 \
            const uint32_t bl1 = bLs[D][nb + 4];                             \
            mma16816(acc[j], ah0, ah1, ah2, ah3, bh0, bh1);                  \
            mma16816(acc[j], ah0, ah1, ah2, ah3, bl0, bl1);                  \
            mma16816(acc[j], al0, al1, al2, al3, bh0, bh1);                  \
        }                                                                    \
    }

    // ---- prologue: chunk0 -> slot A, chunk1 -> slot B, stage chunk0 ----
    FC_LOAD(wA, bvA, 0)
    FC_LOAD(wB, bvB, 1)
    FC_STAGE(wA, bvA, 0)
    __syncthreads();

#pragma unroll 1
    for (int c = 0; c < FC_NCH32; c += 2) {
        // phase A: compute chunk c (buf 0); slot A is free -> load c+2
        if (c + 2 < FC_NCH32) FC_LOAD(wA, bvA, c + 2)
        FC_COMPUTE(0)
        FC_STAGE(wB, bvB, 1)          // stage chunk c+1 (loaded >=1 phase ago)
        __syncthreads();

        // phase B: compute chunk c+1 (buf 1); slot B free -> load c+3
        if (c + 3 < FC_NCH32) FC_LOAD(wB, bvB, c + 3)
        FC_COMPUTE(1)
        if (c + 2 < FC_NCH32) FC_STAGE(wA, bvA, 0)   // stage chunk c+2
        __syncthreads();
    }

    // ---- epilogue: C[m][n] fragments -> g_Cpart ----
    const int m0 = mbase + w * 16 + gr;
#pragma unroll
    for (int j = 0; j < 4; ++j) {
        const int n0 = j * 8 + gc * 2;
        float* d0 = g_Cpart + ((size_t)blockIdx.y * FC_M + m0) * 32 + n0;
        float* d1 = d0 + (size_t)8 * 32;
        *(float2*)d0 = make_float2(acc[j][0], acc[j][1]);
        *(float2*)d1 = make_float2(acc[j][2], acc[j][3]);
    }
#undef FC_LOAD
#undef FC_STAGE
#undef FC_COMPUTE
}

// ---------------------------------------------------------------------------
// 3) reduce split-K + bias + squash -> primary caps output + capsT scratch
// ---------------------------------------------------------------------------
__global__ void caps_kernel(const float* __restrict__ fcb,
                            float* __restrict__ out) {
    int idx = blockIdx.x * 256 + threadIdx.x;   // 36864
    int b = idx & 31;
    int cap = idx >> 5;
    float pc[8];
    float n2 = 0.f;
#pragma unroll
    for (int d = 0; d < 8; ++d) {
        int m = cap * 8 + d;
        float v = fcb[m];
#pragma unroll
        for (int s = 0; s < FC_SPLITK; ++s)
            v += g_Cpart[((size_t)s * FC_M + m) * 32 + b];
        pc[d] = v;
        n2 += v * v;
    }
    float scale = n2 / (1.f + n2);
    float inv = 1.f / sqrtf(n2);
#pragma unroll
    for (int d = 0; d < 8; ++d) {
        float o = scale * (pc[d] * inv + 1e-8f);
        out[OFF_PRIM + (size_t)b * 9216 + cap * 8 + d] = o;
        g_capsT[(cap * 8 + d) * 32 + b] = o;
    }
}

// ---------------------------------------------------------------------------
// 4) u_hat[b,n,p,d] = sum_i W[0,n,p,d,i] * caps[b,p,i] -> g_uhatT[n][p][d][b]
// ---------------------------------------------------------------------------
__global__ void uhat_kernel(const float* __restrict__ W) {
    int idx = blockIdx.x * 256 + threadIdx.x;   // 368640
    int b = idx & 31;
    int r = idx >> 5;                            // n*1152 + p
    int p = r % 1152;
    float caps[8];
#pragma unroll
    for (int i = 0; i < 8; ++i) caps[i] = g_capsT[(p * 8 + i) * 32 + b];
    const float* Wp = W + (size_t)r * 128;       // warp-uniform broadcast
    float* up = g_uhatT + (size_t)r * 512 + b;
#pragma unroll
    for (int d = 0; d < 16; ++d) {
        float a = 0.f;
#pragma unroll
        for (int i = 0; i < 8; ++i) a = fmaf(Wp[d * 8 + i], caps[i], a);
        up[d * 32] = a;
    }
}

// ---------------------------------------------------------------------------
// 5a) partial s sums over p-chunks of 32: spart[n][ch][d][b]
// ---------------------------------------------------------------------------
__global__ void rout_sv_kernel(int uniformC) {
    int n = blockIdx.x / 36;
    int ch = blockIdx.x - n * 36;
    int t = threadIdx.x;                         // 512 = 16 d * 32 b
    int b = t & 31;
    int d = t >> 5;
    int rbase = n * 1152 + ch * 32;
    float a = 0.f;
#pragma unroll 8
    for (int pp = 0; pp < 32; ++pp) {
        size_t r = rbase + pp;
        float c = uniformC ? 0.1f : g_cT[r * 32 + b];
        a = fmaf(c, g_uhatT[(r * 16 + d) * 32 + b], a);
    }
    g_spart[(((size_t)n * 36 + ch) * 16 + d) * 32 + b] = a;
}

// 5b) reduce partials + squash -> v (and digit caps output when final)
__global__ void rout_squash_kernel(int final_, float* __restrict__ out) {
    int t = threadIdx.x;                         // 320
    int b = t & 31;
    int n = t >> 5;
    float s[16];
    float n2 = 0.f;
#pragma unroll
    for (int d = 0; d < 16; ++d) {
        float a = 0.f;
        for (int ch = 0; ch < 36; ++ch)
            a += g_spart[(((size_t)n * 36 + ch) * 16 + d) * 32 + b];
        s[d] = a;
        n2 += a * a;
    }
    float scale = n2 / (1.f + n2);
    float inv = 1.f / sqrtf(n2);
#pragma unroll
    for (int d = 0; d < 16; ++d) {
        float v = scale * (s[d] * inv + 1e-8f);
        g_v[(n * 32 + b) * 16 + d] = v;
        if (final_) out[OFF_DIGIT + (size_t)b * 160 + n * 16 + d] = v;
    }
}

// 5c) b += sum_d u_hat * v   (first iteration: b = uv, since b starts at 0)
__global__ void rout_update_kernel(int first) {
    int idx = blockIdx.x * 256 + threadIdx.x;   // 368640
    int b = idx & 31;
    int r = idx >> 5;
    int n = r / 1152;
    const float* up = g_uhatT + (size_t)r * 512 + b;
    const float* vp = g_v + ((size_t)n * 32 + b) * 16;
    float a = 0.f;
#pragma unroll
    for (int d = 0; d < 16; ++d) a = fmaf(up[d * 32], vp[d], a);
    size_t o = (size_t)r * 32 + b;
    g_bT[o] = (first ? 0.f : g_bT[o]) + a;
}

// 5d) c = softmax over n of b; optionally emit final c and b to output
__global__ void softmax_kernel(int write_out, float* __restrict__ out) {
    int idx = blockIdx.x * 256 + threadIdx.x;   // 36864
    int b = idx & 31;
    int p = idx >> 5;
    float bv[10];
    float m = -1e30f;
#pragma unroll
    for (int n = 0; n < 10; ++n) {
        bv[n] = g_bT[((size_t)n * 1152 + p) * 32 + b];
        m = fmaxf(m, bv[n]);
    }
    float e[10];
    float sum = 0.f;
#pragma unroll
    for (int n = 0; n < 10; ++n) {
        e[n] = expf(bv[n] - m);
        sum += e[n];
    }
    float invs = 1.f / sum;
#pragma unroll
    for (int n = 0; n < 10; ++n) {
        float c = e[n] * invs;
        g_cT[((size_t)n * 1152 + p) * 32 + b] = c;
        if (write_out) {
            out[OFF_C + ((size_t)b * 10 + n) * 1152 + p] = c;
            out[OFF_B + ((size_t)b * 10 + n) * 1152 + p] = bv[n];
        }
    }
}

// ---------------------------------------------------------------------------
// 6) logits = ||digit||, argmax (first max), masked -> g_masked[i][b]
// ---------------------------------------------------------------------------
__global__ void logits_kernel(float* __restrict__ out) {
    int b = threadIdx.x;                         // 32
    float dg[160];
    for (int i = 0; i < 160; ++i) dg[i] = out[OFF_DIGIT + (size_t)b * 160 + i];
    float best = -1.f;
    int am = 0;
    for (int n = 0; n < 10; ++n) {
        float n2 = 0.f;
        for (int d = 0; d < 16; ++d) {
            float v = dg[n * 16 + d];
            n2 += v * v;
        }
        float lg = sqrtf(n2);
        out[OFF_LOGITS + b * 10 + n] = lg;
        if (lg > best) { best = lg; am = n; }
    }
    for (int n = 0; n < 10; ++n)
        for (int d = 0; d < 16; ++d)
            g_masked[(n * 16 + d) * 32 + b] = (n == am) ? dg[n * 16 + d] : 0.f;
}

// ---------------------------------------------------------------------------
// 7) decoder MLP
// ---------------------------------------------------------------------------
__global__ void dec1_kernel(const float* __restrict__ Wt,
                            const float* __restrict__ bias) {
    int idx = blockIdx.x * 256 + threadIdx.x;   // 512*32
    int b = idx & 31, o = idx >> 5;
    const float* w = Wt + (size_t)o * 160;
    float a0 = 0.f, a1 = 0.f, a2 = 0.f, a3 = 0.f;
#pragma unroll 4
    for (int i = 0; i < 160; i += 4) {
        a0 = fmaf(w[i],     g_masked[(i)     * 32 + b], a0);
        a1 = fmaf(w[i + 1], g_masked[(i + 1) * 32 + b], a1);
        a2 = fmaf(w[i + 2], g_masked[(i + 2) * 32 + b], a2);
        a3 = fmaf(w[i + 3], g_masked[(i + 3) * 32 + b], a3);
    }
    g_d1[o * 32 + b] = fmaxf(bias[o] + ((a0 + a1) + (a2 + a3)), 0.f);
}

__global__ void dec2_kernel(const float* __restrict__ Wt,
                            const float* __restrict__ bias) {
    int idx = blockIdx.x * 256 + threadIdx.x;   // 1024*32
    int b = idx & 31, o = idx >> 5;
    const float* w = Wt + (size_t)o * 512;
    float a0 = 0.f, a1 = 0.f, a2 = 0.f, a3 = 0.f;
#pragma unroll 4
    for (int i = 0; i < 512; i += 4) {
        a0 = fmaf(w[i],     g_d1[(i)     * 32 + b], a0);
        a1 = fmaf(w[i + 1], g_d1[(i + 1) * 32 + b], a1);
        a2 = fmaf(w[i + 2], g_d1[(i + 2) * 32 + b], a2);
        a3 = fmaf(w[i + 3], g_d1[(i + 3) * 32 + b], a3);
    }
    g_d2[o * 32 + b] = fmaxf(bias[o] + ((a0 + a1) + (a2 + a3)), 0.f);
}

__global__ void dec3_kernel(const float* __restrict__ Wt,
                            const float* __restrict__ bias,
                            float* __restrict__ out) {
    int idx = blockIdx.x * 256 + threadIdx.x;   // 784*32
    int b = idx & 31, o = idx >> 5;
    const float* w = Wt + (size_t)o * 1024;
    float a0 = 0.f, a1 = 0.f, a2 = 0.f, a3 = 0.f;
#pragma unroll 4
    for (int i = 0; i < 1024; i += 4) {
        a0 = fmaf(w[i],     g_d2[(i)     * 32 + b], a0);
        a1 = fmaf(w[i + 1], g_d2[(i + 1) * 32 + b], a1);
        a2 = fmaf(w[i + 2], g_d2[(i + 2) * 32 + b], a2);
        a3 = fmaf(w[i + 3], g_d2[(i + 3) * 32 + b], a3);
    }
    float x = bias[o] + ((a0 + a1) + (a2 + a3));
    out[OFF_RECON + (size_t)b * 784 + o] = 1.f / (1.f + expf(-x));
}

// ---------------------------------------------------------------------------
// Resolve inputs by (unique) element count — order-independent binding.
// ---------------------------------------------------------------------------
static const float* by_size(void* const* d_in, const int* s, int n, int want) {
    for (int i = 0; i < n; ++i)
        if (s[i] == want) return (const float*)d_in[i];
    return nullptr;
}

extern "C" void kernel_launch(void* const* d_in, const int* in_sizes, int n_in,
                              void* d_out, int out_size) {
    const float* x   = by_size(d_in, in_sizes, n_in, 32 * 784);        // 25088
    const float* cw  = by_size(d_in, in_sizes, n_in, 256 * 81);        // 20736
    const float* cb  = by_size(d_in, in_sizes, n_in, 256);
    const float* fcw = by_size(d_in, in_sizes, n_in, 943718400);       // 9216*102400
    const float* fcb = by_size(d_in, in_sizes, n_in, 9216);
    const float* W   = by_size(d_in, in_sizes, n_in, 1474560);         // 10*1152*16*8
    const float* d1w = by_size(d_in, in_sizes, n_in, 512 * 160);       // 81920
    const float* d1b = by_size(d_in, in_sizes, n_in, 512);
    const float* d2w = by_size(d_in, in_sizes, n_in, 1024 * 512);      // 524288
    const float* d2b = by_size(d_in, in_sizes, n_in, 1024);
    const float* d3w = by_size(d_in, in_sizes, n_in, 784 * 1024);      // 802816
    const float* d3b = by_size(d_in, in_sizes, n_in, 784);
    float* out = (float*)d_out;

    xT_kernel<<<98, 256>>>(x);                           // launch 1
    conv_kernel<<<12800, 256>>>(cw, cb);                 // launch 2
    actcvt_kernel<<<12800, 256>>>();                     // launch 3
    fc_hmma_kernel<<<dim3(72, 8), 256>>>(fcw);           // launch 4 <- ncu slot
    caps_kernel<<<144, 256>>>(fcb, out);
    uhat_kernel<<<1440, 256>>>(W);

    // routing iteration 0 (c = softmax(0) = 0.1 uniform)
    rout_sv_kernel<<<360, 512>>>(1);
    rout_squash_kernel<<<1, 320>>>(0, out);
    rout_update_kernel<<<1440, 256>>>(1);
    // routing iteration 1
    softmax_kernel<<<144, 256>>>(0, out);
    rout_sv_kernel<<<360, 512>>>(0);
    rout_squash_kernel<<<1, 320>>>(0, out);
    rout_update_kernel<<<1440, 256>>>(0);
    // final pass (emit c, b, digit caps)
    softmax_kernel<<<144, 256>>>(1, out);
    rout_sv_kernel<<<360, 512>>>(0);
    rout_squash_kernel<<<1, 320>>>(1, out);

    logits_kernel<<<1, 32>>>(out);
    dec1_kernel<<<64, 256>>>(d1w, d1b);
    dec2_kernel<<<128, 256>>>(d2w, d2b);
    dec3_kernel<<<98, 256>>>(d3w, d3b, out);
}

// round 16
// speedup vs baseline: 2.2652x; 1.2153x over previous
#include <cuda_runtime.h>
#include <cuda_bf16.h>
#include <math.h>
#include <stdint.h>

// ---------------------------------------------------------------------------
// CapsNet forward, B=32. Dominant cost: FC 102400->9216 (3.77 GB weights).
// R16: mma.sync bf16 hi/lo FC, BM=256 with m32 warp tiles (halves b-frag
// redundancy), cp.async.cg staging of raw fp32 weights (no LDG->STS round
// trip, no staging registers), hi/lo split done in the consumer from one
// fp32 LDS.64. R15 was L1-wavefront-bound at 75.9%.
// ---------------------------------------------------------------------------

#define FC_M      9216
#define FC_K      102400
#define FC_SPLITK 8
#define FC_KSEG   12800     // FC_K / FC_SPLITK
#define FC_NCH32  400       // FC_KSEG / 32
#define WST       40        // weight smem row stride (fp32 words; 8*gr bank map)
#define BST       20        // act smem row stride (bf16x2 words; proven layout)

// output section offsets (concatenated tuple, fp32)
#define OFF_LOGITS 0
#define OFF_RECON  320
#define OFF_PRIM   25408
#define OFF_DIGIT  320320
#define OFF_C      325440
#define OFF_B      694080

// ---------------- device scratch (static; allocations are forbidden) -------
__device__ __align__(16) float g_xT[784 * 32];
__device__ __align__(16) float g_flatT[FC_K * 32];                 // 13.1 MB
__device__ __align__(16) __nv_bfloat16 g_actH[32 * FC_K];          //  6.6 MB
__device__ __align__(16) __nv_bfloat16 g_actL[32 * FC_K];          //  6.6 MB
__device__ __align__(16) float g_Cpart[FC_SPLITK * FC_M * 32];     //  9.4 MB
__device__ __align__(16) float g_capsT[FC_M * 32];
__device__ __align__(16) float g_uhatT[10 * 1152 * 16 * 32];       // 23.6 MB
__device__ __align__(16) float g_bT[10 * 1152 * 32];
__device__ __align__(16) float g_cT[10 * 1152 * 32];
__device__ __align__(16) float g_spart[10 * 36 * 16 * 32];
__device__ __align__(16) float g_v[10 * 32 * 16];
__device__ __align__(16) float g_masked[160 * 32];
__device__ __align__(16) float g_d1[512 * 32];
__device__ __align__(16) float g_d2[1024 * 32];

// ---------------- helpers ---------------------------------------------------
__device__ __forceinline__ uint32_t smem_u32(const void* p) {
    uint32_t a;
    asm("{ .reg .u64 t; cvta.to.shared.u64 t, %1; cvt.u32.u64 %0, t; }"
        : "=r"(a) : "l"(p));
    return a;
}
__device__ __forceinline__ void cp16(uint32_t dst, const void* src) {
    asm volatile("cp.async.cg.shared.global [%0], [%1], 16;"
                 :: "r"(dst), "l"(src));
}
__device__ __forceinline__ void cp_commit() {
    asm volatile("cp.async.commit_group;" ::: "memory");
}
__device__ __forceinline__ void cp_wait0() {
    asm volatile("cp.async.wait_group 0;" ::: "memory");
}
// split a float2 into bf16x2 hi + bf16x2 lo
__device__ __forceinline__ void split_f2(float2 f, uint32_t& hi, uint32_t& lo) {
    __nv_bfloat162 h = __floats2bfloat162_rn(f.x, f.y);
    float2 hf = __bfloat1622float2(h);
    __nv_bfloat162 l = __floats2bfloat162_rn(f.x - hf.x, f.y - hf.y);
    hi = *reinterpret_cast<uint32_t*>(&h);
    lo = *reinterpret_cast<uint32_t*>(&l);
}
// mma.sync m16n8k16 row.col f32.bf16.bf16.f32 (arch-generic, sm_80+)
__device__ __forceinline__ void mma16816(float* c,
                                         uint32_t a0, uint32_t a1,
                                         uint32_t a2, uint32_t a3,
                                         uint32_t b0, uint32_t b1) {
    asm volatile(
        "mma.sync.aligned.m16n8k16.row.col.f32.bf16.bf16.f32 "
        "{%0,%1,%2,%3}, {%4,%5,%6,%7}, {%8,%9}, {%0,%1,%2,%3};"
        : "+f"(c[0]), "+f"(c[1]), "+f"(c[2]), "+f"(c[3])
        : "r"(a0), "r"(a1), "r"(a2), "r"(a3), "r"(b0), "r"(b1));
}

// ---------------------------------------------------------------------------
// 0) x [32][784] -> xT [784][32]
// ---------------------------------------------------------------------------
__global__ void xT_kernel(const float* __restrict__ x) {
    int idx = blockIdx.x * 256 + threadIdx.x;
    if (idx < 784 * 32) {
        int b = idx / 784;
        int pix = idx - b * 784;
        g_xT[pix * 32 + b] = x[idx];
    }
}

// ---------------------------------------------------------------------------
// 1) conv 9x9 VALID + bias + relu -> flatT[k][b]
// ---------------------------------------------------------------------------
__global__ void conv_kernel(const float* __restrict__ cw,
                            const float* __restrict__ cb) {
    int idx = blockIdx.x * 256 + threadIdx.x;
    int b = idx & 31;
    int k = idx >> 5;
    int oc = k / 400;
    int pos = k - oc * 400;
    int oh = pos / 20;
    int ow = pos - oh * 20;
    float acc = cb[oc];
    const float* wp = cw + oc * 81;
#pragma unroll
    for (int r = 0; r < 9; ++r) {
#pragma unroll
        for (int cc = 0; cc < 9; ++cc) {
            acc = fmaf(g_xT[((oh + r) * 28 + ow + cc) * 32 + b], wp[r * 9 + cc], acc);
        }
    }
    g_flatT[(size_t)k * 32 + b] = fmaxf(acc, 0.f);
}

// ---------------------------------------------------------------------------
// 1b) act hi/lo bf16 split: flatT[k][b] -> actH/actL[b][k]
// ---------------------------------------------------------------------------
__global__ void actcvt_kernel() {
    int idx = blockIdx.x * 256 + threadIdx.x;    // 3,276,800
    int b = idx / FC_K;
    int k = idx - b * FC_K;
    float f = g_flatT[(size_t)k * 32 + b];
    __nv_bfloat16 h = __float2bfloat16_rn(f);
    g_actH[(size_t)b * FC_K + k] = h;
    g_actL[(size_t)b * FC_K + k] = __float2bfloat16_rn(f - __bfloat162float(h));
}

// ---------------------------------------------------------------------------
// 2) FC via mma.sync bf16 hi/lo: Cpart[sk][m][b] = sum_k W[m][k]*act[b][k]
//    Block 256 = 8 warps, BM=256 (m32/warp), N=32 (4 n8), BK=32.
//    Weights cp.async'd as raw fp32 into stride-40 smem rows; fragments read
//    via LDS.64 (conflict-free per half-warp) and split to hi/lo in regs.
//    Acts cp.async'd as pre-split bf16 into the proven stride-20 layout.
// ---------------------------------------------------------------------------
__global__ void __launch_bounds__(256, 2)
fc_hmma_kernel(const float* __restrict__ fcw) {
    __shared__ __align__(16) float    wS[2][256 * WST];   // 80 KB
    __shared__ __align__(16) uint32_t bHs[2][32 * BST];   //  5 KB
    __shared__ __align__(16) uint32_t bLs[2][32 * BST];   //  5 KB

    const int t = threadIdx.x;
    const int mbase = blockIdx.x * 256;
    const long long kbase = (long long)blockIdx.y * FC_KSEG;

    // ---- cp.async geometry ----
    // weights: 2048 16B transfers/chunk; id = t + 256*j -> row=(id>>3), kq=id&7
    const int wrow0 = t >> 3;                // base row (0..31), +32 per j
    const int wkq = t & 7;                   // 16B group within the 128B row
    const float* wsrc0 = fcw + (size_t)(mbase + wrow0) * FC_K + kbase + wkq * 4;
    const size_t wjstr = (size_t)32 * FC_K;
    // acts: 256 transfers/chunk; t>>7 -> H/L, n=(t&127)>>2, kq=t&3
    const int an = (t & 127) >> 2;
    const int akq = t & 3;
    const __nv_bfloat16* asrc =
        ((t >> 7) ? g_actL : g_actH) + (size_t)an * FC_K + kbase + akq * 8;

    uint32_t wdstB[2], adstB[2];
#pragma unroll
    for (int u = 0; u < 2; ++u) {
        wdstB[u] = smem_u32(&wS[u][wrow0 * WST + wkq * 4]);
        adstB[u] = (t >> 7) ? smem_u32(&bLs[u][an * BST + akq * 4])
                            : smem_u32(&bHs[u][an * BST + akq * 4]);
    }

#define FC_ISSUE(C, D)                                                       \
    {                                                                        \
        const float* p = wsrc0 + (size_t)(C) * 32;                           \
        _Pragma("unroll")                                                    \
        for (int j = 0; j < 8; ++j)                                          \
            cp16(wdstB[D] + j * (32 * WST * 4), p + j * wjstr);              \
        cp16(adstB[D], asrc + (size_t)(C) * 32);                             \
        cp_commit();                                                         \
    }

    // ---- compute geometry ----
    const int w = t >> 5;                    // warp: rows w*32 .. w*32+31
    const int lane = t & 31;
    const int gr = lane >> 2;                // 0..7
    const int gc = lane & 3;                 // 0..3

    float acc[2][4][4];
#pragma unroll
    for (int mt = 0; mt < 2; ++mt)
#pragma unroll
        for (int j = 0; j < 4; ++j)
#pragma unroll
            for (int q = 0; q < 4; ++q) acc[mt][j][q] = 0.f;

#define FC_COMPUTE(D)                                                        \
    _Pragma("unroll")                                                        \
    for (int s = 0; s < 2; ++s) {                                            \
        uint32_t bh[4][2], bl[4][2];                                         \
        _Pragma("unroll")                                                    \
        for (int j = 0; j < 4; ++j) {                                        \
            const int nb = (j * 8 + gr) * BST + s * 8 + gc;                  \
            bh[j][0] = bHs[D][nb]; bh[j][1] = bHs[D][nb + 4];                \
            bl[j][0] = bLs[D][nb]; bl[j][1] = bLs[D][nb + 4];                \
        }                                                                    \
        _Pragma("unroll")                                                    \
        for (int mt = 0; mt < 2; ++mt) {                                     \
            const int rb = (w * 32 + mt * 16 + gr) * WST + s * 16 + 2 * gc;  \
            float2 f0 = *(const float2*)&wS[D][rb];                          \
            float2 f1 = *(const float2*)&wS[D][rb + 8 * WST];                \
            float2 f2 = *(const float2*)&wS[D][rb + 8];                      \
            float2 f3 = *(const float2*)&wS[D][rb + 8 * WST + 8];            \
            uint32_t ah0, ah1, ah2, ah3, al0, al1, al2, al3;                 \
            split_f2(f0, ah0, al0); split_f2(f1, ah1, al1);                  \
            split_f2(f2, ah2, al2); split_f2(f3, ah3, al3);                  \
            _Pragma("unroll")                                                \
            for (int j = 0; j < 4; ++j) {                                    \
                mma16816(acc[mt][j], ah0, ah1, ah2, ah3, bh[j][0], bh[j][1]);\
                mma16816(acc[mt][j], ah0, ah1, ah2, ah3, bl[j][0], bl[j][1]);\
                mma16816(acc[mt][j], al0, al1, al2, al3, bh[j][0], bh[j][1]);\
            }                                                                \
        }                                                                    \
    }

    // ---- prologue ----
    FC_ISSUE(0, 0)
    cp_wait0();
    __syncthreads();

#pragma unroll 1
    for (int c = 0; c < FC_NCH32; ++c) {
        const int buf = c & 1;
        if (c + 1 < FC_NCH32) FC_ISSUE(c + 1, buf ^ 1)
        FC_COMPUTE(buf)
        if (c + 1 < FC_NCH32) cp_wait0();
        __syncthreads();
    }

    // ---- epilogue: fragments -> g_Cpart ----
#pragma unroll
    for (int mt = 0; mt < 2; ++mt) {
        const int m0 = mbase + w * 32 + mt * 16 + gr;
#pragma unroll
        for (int j = 0; j < 4; ++j) {
            const int n0 = j * 8 + gc * 2;
            float* d0 = g_Cpart + ((size_t)blockIdx.y * FC_M + m0) * 32 + n0;
            float* d1 = d0 + (size_t)8 * 32;
            *(float2*)d0 = make_float2(acc[mt][j][0], acc[mt][j][1]);
            *(float2*)d1 = make_float2(acc[mt][j][2], acc[mt][j][3]);
        }
    }
#undef FC_ISSUE
#undef FC_COMPUTE
}

// ---------------------------------------------------------------------------
// 3) reduce split-K + bias + squash -> primary caps output + capsT scratch
// ---------------------------------------------------------------------------
__global__ void caps_kernel(const float* __restrict__ fcb,
                            float* __restrict__ out) {
    int idx = blockIdx.x * 256 + threadIdx.x;   // 36864
    int b = idx & 31;
    int cap = idx >> 5;
    float pc[8];
    float n2 = 0.f;
#pragma unroll
    for (int d = 0; d < 8; ++d) {
        int m = cap * 8 + d;
        float v = fcb[m];
#pragma unroll
        for (int s = 0; s < FC_SPLITK; ++s)
            v += g_Cpart[((size_t)s * FC_M + m) * 32 + b];
        pc[d] = v;
        n2 += v * v;
    }
    float scale = n2 / (1.f + n2);
    float inv = 1.f / sqrtf(n2);
#pragma unroll
    for (int d = 0; d < 8; ++d) {
        float o = scale * (pc[d] * inv + 1e-8f);
        out[OFF_PRIM + (size_t)b * 9216 + cap * 8 + d] = o;
        g_capsT[(cap * 8 + d) * 32 + b] = o;
    }
}

// ---------------------------------------------------------------------------
// 4) u_hat[b,n,p,d] = sum_i W[0,n,p,d,i] * caps[b,p,i] -> g_uhatT[n][p][d][b]
// ---------------------------------------------------------------------------
__global__ void uhat_kernel(const float* __restrict__ W) {
    int idx = blockIdx.x * 256 + threadIdx.x;   // 368640
    int b = idx & 31;
    int r = idx >> 5;                            // n*1152 + p
    int p = r % 1152;
    float caps[8];
#pragma unroll
    for (int i = 0; i < 8; ++i) caps[i] = g_capsT[(p * 8 + i) * 32 + b];
    const float* Wp = W + (size_t)r * 128;       // warp-uniform broadcast
    float* up = g_uhatT + (size_t)r * 512 + b;
#pragma unroll
    for (int d = 0; d < 16; ++d) {
        float a = 0.f;
#pragma unroll
        for (int i = 0; i < 8; ++i) a = fmaf(Wp[d * 8 + i], caps[i], a);
        up[d * 32] = a;
    }
}

// ---------------------------------------------------------------------------
// 5a) partial s sums over p-chunks of 32: spart[n][ch][d][b]
// ---------------------------------------------------------------------------
__global__ void rout_sv_kernel(int uniformC) {
    int n = blockIdx.x / 36;
    int ch = blockIdx.x - n * 36;
    int t = threadIdx.x;                         // 512 = 16 d * 32 b
    int b = t & 31;
    int d = t >> 5;
    int rbase = n * 1152 + ch * 32;
    float a = 0.f;
#pragma unroll 8
    for (int pp = 0; pp < 32; ++pp) {
        size_t r = rbase + pp;
        float c = uniformC ? 0.1f : g_cT[r * 32 + b];
        a = fmaf(c, g_uhatT[(r * 16 + d) * 32 + b], a);
    }
    g_spart[(((size_t)n * 36 + ch) * 16 + d) * 32 + b] = a;
}

// 5b) reduce partials + squash -> v (and digit caps output when final)
__global__ void rout_squash_kernel(int final_, float* __restrict__ out) {
    int t = threadIdx.x;                         // 320
    int b = t & 31;
    int n = t >> 5;
    float s[16];
    float n2 = 0.f;
#pragma unroll
    for (int d = 0; d < 16; ++d) {
        float a = 0.f;
        for (int ch = 0; ch < 36; ++ch)
            a += g_spart[(((size_t)n * 36 + ch) * 16 + d) * 32 + b];
        s[d] = a;
        n2 += a * a;
    }
    float scale = n2 / (1.f + n2);
    float inv = 1.f / sqrtf(n2);
#pragma unroll
    for (int d = 0; d < 16; ++d) {
        float v = scale * (s[d] * inv + 1e-8f);
        g_v[(n * 32 + b) * 16 + d] = v;
        if (final_) out[OFF_DIGIT + (size_t)b * 160 + n * 16 + d] = v;
    }
}

// 5c) b += sum_d u_hat * v   (first iteration: b = uv, since b starts at 0)
__global__ void rout_update_kernel(int first) {
    int idx = blockIdx.x * 256 + threadIdx.x;   // 368640
    int b = idx & 31;
    int r = idx >> 5;
    int n = r / 1152;
    const float* up = g_uhatT + (size_t)r * 512 + b;
    const float* vp = g_v + ((size_t)n * 32 + b) * 16;
    float a = 0.f;
#pragma unroll
    for (int d = 0; d < 16; ++d) a = fmaf(up[d * 32], vp[d], a);
    size_t o = (size_t)r * 32 + b;
    g_bT[o] = (first ? 0.f : g_bT[o]) + a;
}

// 5d) c = softmax over n of b; optionally emit final c and b to output
__global__ void softmax_kernel(int write_out, float* __restrict__ out) {
    int idx = blockIdx.x * 256 + threadIdx.x;   // 36864
    int b = idx & 31;
    int p = idx >> 5;
    float bv[10];
    float m = -1e30f;
#pragma unroll
    for (int n = 0; n < 10; ++n) {
        bv[n] = g_bT[((size_t)n * 1152 + p) * 32 + b];
        m = fmaxf(m, bv[n]);
    }
    float e[10];
    float sum = 0.f;
#pragma unroll
    for (int n = 0; n < 10; ++n) {
        e[n] = expf(bv[n] - m);
        sum += e[n];
    }
    float invs = 1.f / sum;
#pragma unroll
    for (int n = 0; n < 10; ++n) {
        float c = e[n] * invs;
        g_cT[((size_t)n * 1152 + p) * 32 + b] = c;
        if (write_out) {
            out[OFF_C + ((size_t)b * 10 + n) * 1152 + p] = c;
            out[OFF_B + ((size_t)b * 10 + n) * 1152 + p] = bv[n];
        }
    }
}

// ---------------------------------------------------------------------------
// 6) logits = ||digit||, argmax (first max), masked -> g_masked[i][b]
// ---------------------------------------------------------------------------
__global__ void logits_kernel(float* __restrict__ out) {
    int b = threadIdx.x;                         // 32
    float dg[160];
    for (int i = 0; i < 160; ++i) dg[i] = out[OFF_DIGIT + (size_t)b * 160 + i];
    float best = -1.f;
    int am = 0;
    for (int n = 0; n < 10; ++n) {
        float n2 = 0.f;
        for (int d = 0; d < 16; ++d) {
            float v = dg[n * 16 + d];
            n2 += v * v;
        }
        float lg = sqrtf(n2);
        out[OFF_LOGITS + b * 10 + n] = lg;
        if (lg > best) { best = lg; am = n; }
    }
    for (int n = 0; n < 10; ++n)
        for (int d = 0; d < 16; ++d)
            g_masked[(n * 16 + d) * 32 + b] = (n == am) ? dg[n * 16 + d] : 0.f;
}

// ---------------------------------------------------------------------------
// 7) decoder MLP
// ---------------------------------------------------------------------------
__global__ void dec1_kernel(const float* __restrict__ Wt,
                            const float* __restrict__ bias) {
    int idx = blockIdx.x * 256 + threadIdx.x;   // 512*32
    int b = idx & 31, o = idx >> 5;
    const float* w = Wt + (size_t)o * 160;
    float a0 = 0.f, a1 = 0.f, a2 = 0.f, a3 = 0.f;
#pragma unroll 4
    for (int i = 0; i < 160; i += 4) {
        a0 = fmaf(w[i],     g_masked[(i)     * 32 + b], a0);
        a1 = fmaf(w[i + 1], g_masked[(i + 1) * 32 + b], a1);
        a2 = fmaf(w[i + 2], g_masked[(i + 2) * 32 + b], a2);
        a3 = fmaf(w[i + 3], g_masked[(i + 3) * 32 + b], a3);
    }
    g_d1[o * 32 + b] = fmaxf(bias[o] + ((a0 + a1) + (a2 + a3)), 0.f);
}

__global__ void dec2_kernel(const float* __restrict__ Wt,
                            const float* __restrict__ bias) {
    int idx = blockIdx.x * 256 + threadIdx.x;   // 1024*32
    int b = idx & 31, o = idx >> 5;
    const float* w = Wt + (size_t)o * 512;
    float a0 = 0.f, a1 = 0.f, a2 = 0.f, a3 = 0.f;
#pragma unroll 4
    for (int i = 0; i < 512; i += 4) {
        a0 = fmaf(w[i],     g_d1[(i)     * 32 + b], a0);
        a1 = fmaf(w[i + 1], g_d1[(i + 1) * 32 + b], a1);
        a2 = fmaf(w[i + 2], g_d1[(i + 2) * 32 + b], a2);
        a3 = fmaf(w[i + 3], g_d1[(i + 3) * 32 + b], a3);
    }
    g_d2[o * 32 + b] = fmaxf(bias[o] + ((a0 + a1) + (a2 + a3)), 0.f);
}

__global__ void dec3_kernel(const float* __restrict__ Wt,
                            const float* __restrict__ bias,
                            float* __restrict__ out) {
    int idx = blockIdx.x * 256 + threadIdx.x;   // 784*32
    int b = idx & 31, o = idx >> 5;
    const float* w = Wt + (size_t)o * 1024;
    float a0 = 0.f, a1 = 0.f, a2 = 0.f, a3 = 0.f;
#pragma unroll 4
    for (int i = 0; i < 1024; i += 4) {
        a0 = fmaf(w[i],     g_d2[(i)     * 32 + b], a0);
        a1 = fmaf(w[i + 1], g_d2[(i + 1) * 32 + b], a1);
        a2 = fmaf(w[i + 2], g_d2[(i + 2) * 32 + b], a2);
        a3 = fmaf(w[i + 3], g_d2[(i + 3) * 32 + b], a3);
    }
    float x = bias[o] + ((a0 + a1) + (a2 + a3));
    out[OFF_RECON + (size_t)b * 784 + o] = 1.f / (1.f + expf(-x));
}

// ---------------------------------------------------------------------------
// Resolve inputs by (unique) element count — order-independent binding.
// ---------------------------------------------------------------------------
static const float* by_size(void* const* d_in, const int* s, int n, int want) {
    for (int i = 0; i < n; ++i)
        if (s[i] == want) return (const float*)d_in[i];
    return nullptr;
}

extern "C" void kernel_launch(void* const* d_in, const int* in_sizes, int n_in,
                              void* d_out, int out_size) {
    const float* x   = by_size(d_in, in_sizes, n_in, 32 * 784);        // 25088
    const float* cw  = by_size(d_in, in_sizes, n_in, 256 * 81);        // 20736
    const float* cb  = by_size(d_in, in_sizes, n_in, 256);
    const float* fcw = by_size(d_in, in_sizes, n_in, 943718400);       // 9216*102400
    const float* fcb = by_size(d_in, in_sizes, n_in, 9216);
    const float* W   = by_size(d_in, in_sizes, n_in, 1474560);         // 10*1152*16*8
    const float* d1w = by_size(d_in, in_sizes, n_in, 512 * 160);       // 81920
    const float* d1b = by_size(d_in, in_sizes, n_in, 512);
    const float* d2w = by_size(d_in, in_sizes, n_in, 1024 * 512);      // 524288
    const float* d2b = by_size(d_in, in_sizes, n_in, 1024);
    const float* d3w = by_size(d_in, in_sizes, n_in, 784 * 1024);      // 802816
    const float* d3b = by_size(d_in, in_sizes, n_in, 784);
    float* out = (float*)d_out;

    xT_kernel<<<98, 256>>>(x);                           // launch 1
    conv_kernel<<<12800, 256>>>(cw, cb);                 // launch 2
    actcvt_kernel<<<12800, 256>>>();                     // launch 3
    fc_hmma_kernel<<<dim3(36, 8), 256>>>(fcw);           // launch 4 <- ncu slot
    caps_kernel<<<144, 256>>>(fcb, out);
    uhat_kernel<<<1440, 256>>>(W);

    // routing iteration 0 (c = softmax(0) = 0.1 uniform)
    rout_sv_kernel<<<360, 512>>>(1);
    rout_squash_kernel<<<1, 320>>>(0, out);
    rout_update_kernel<<<1440, 256>>>(1);
    // routing iteration 1
    softmax_kernel<<<144, 256>>>(0, out);
    rout_sv_kernel<<<360, 512>>>(0);
    rout_squash_kernel<<<1, 320>>>(0, out);
    rout_update_kernel<<<1440, 256>>>(0);
    // final pass (emit c, b, digit caps)
    softmax_kernel<<<144, 256>>>(1, out);
    rout_sv_kernel<<<360, 512>>>(0);
    rout_squash_kernel<<<1, 320>>>(1, out);

    logits_kernel<<<1, 32>>>(out);
    dec1_kernel<<<64, 256>>>(d1w, d1b);
    dec2_kernel<<<128, 256>>>(d2w, d2b);
    dec3_kernel<<<98, 256>>>(d3w, d3b, out);
}

// round 17
// speedup vs baseline: 2.3249x; 1.0264x over previous
#include <cuda_runtime.h>
#include <cuda_bf16.h>
#include <math.h>
#include <stdint.h>

// ---------------------------------------------------------------------------
// CapsNet forward, B=32. Dominant cost: FC 102400->9216 (3.77 GB weights).
// R17: 3-stage cp.async ring (wait_group 1) so the weight stream never drains
// at chunk boundaries (R16 was DRAM-bound at 68% with a drain every chunk).
// BK=16, WST=24 (bank-conflict-free fragment reads), BST=12 act tiles.
// ---------------------------------------------------------------------------

#define FC_M      9216
#define FC_K      102400
#define FC_SPLITK 8
#define FC_KSEG   12800     // FC_K / FC_SPLITK
#define FC_NCH    800       // FC_KSEG / 16
#define WST       24        // weight smem row stride (fp32 words; 16 + pad 8)
#define BST       12        // act smem row stride (bf16x2 words; proven R13)

// output section offsets (concatenated tuple, fp32)
#define OFF_LOGITS 0
#define OFF_RECON  320
#define OFF_PRIM   25408
#define OFF_DIGIT  320320
#define OFF_C      325440
#define OFF_B      694080

// ---------------- device scratch (static; allocations are forbidden) -------
__device__ __align__(16) float g_xT[784 * 32];
__device__ __align__(16) float g_flatT[FC_K * 32];                 // 13.1 MB
__device__ __align__(16) __nv_bfloat16 g_actH[32 * FC_K];          //  6.6 MB
__device__ __align__(16) __nv_bfloat16 g_actL[32 * FC_K];          //  6.6 MB
__device__ __align__(16) float g_Cpart[FC_SPLITK * FC_M * 32];     //  9.4 MB
__device__ __align__(16) float g_capsT[FC_M * 32];
__device__ __align__(16) float g_uhatT[10 * 1152 * 16 * 32];       // 23.6 MB
__device__ __align__(16) float g_bT[10 * 1152 * 32];
__device__ __align__(16) float g_cT[10 * 1152 * 32];
__device__ __align__(16) float g_spart[10 * 36 * 16 * 32];
__device__ __align__(16) float g_v[10 * 32 * 16];
__device__ __align__(16) float g_masked[160 * 32];
__device__ __align__(16) float g_d1[512 * 32];
__device__ __align__(16) float g_d2[1024 * 32];

// ---------------- helpers ---------------------------------------------------
__device__ __forceinline__ uint32_t smem_u32(const void* p) {
    uint32_t a;
    asm("{ .reg .u64 t; cvta.to.shared.u64 t, %1; cvt.u32.u64 %0, t; }"
        : "=r"(a) : "l"(p));
    return a;
}
__device__ __forceinline__ void cp16(uint32_t dst, const void* src) {
    asm volatile("cp.async.cg.shared.global [%0], [%1], 16;"
                 :: "r"(dst), "l"(src));
}
__device__ __forceinline__ void cp_commit() {
    asm volatile("cp.async.commit_group;" ::: "memory");
}
__device__ __forceinline__ void cp_wait1() {
    asm volatile("cp.async.wait_group 1;" ::: "memory");
}
__device__ __forceinline__ void cp_wait0() {
    asm volatile("cp.async.wait_group 0;" ::: "memory");
}
// split a float2 into bf16x2 hi + bf16x2 lo
__device__ __forceinline__ void split_f2(float2 f, uint32_t& hi, uint32_t& lo) {
    __nv_bfloat162 h = __floats2bfloat162_rn(f.x, f.y);
    float2 hf = __bfloat1622float2(h);
    __nv_bfloat162 l = __floats2bfloat162_rn(f.x - hf.x, f.y - hf.y);
    hi = *reinterpret_cast<uint32_t*>(&h);
    lo = *reinterpret_cast<uint32_t*>(&l);
}
// mma.sync m16n8k16 row.col f32.bf16.bf16.f32 (arch-generic, sm_80+)
__device__ __forceinline__ void mma16816(float* c,
                                         uint32_t a0, uint32_t a1,
                                         uint32_t a2, uint32_t a3,
                                         uint32_t b0, uint32_t b1) {
    asm volatile(
        "mma.sync.aligned.m16n8k16.row.col.f32.bf16.bf16.f32 "
        "{%0,%1,%2,%3}, {%4,%5,%6,%7}, {%8,%9}, {%0,%1,%2,%3};"
        : "+f"(c[0]), "+f"(c[1]), "+f"(c[2]), "+f"(c[3])
        : "r"(a0), "r"(a1), "r"(a2), "r"(a3), "r"(b0), "r"(b1));
}

// ---------------------------------------------------------------------------
// 0) x [32][784] -> xT [784][32]
// ---------------------------------------------------------------------------
__global__ void xT_kernel(const float* __restrict__ x) {
    int idx = blockIdx.x * 256 + threadIdx.x;
    if (idx < 784 * 32) {
        int b = idx / 784;
        int pix = idx - b * 784;
        g_xT[pix * 32 + b] = x[idx];
    }
}

// ---------------------------------------------------------------------------
// 1) conv 9x9 VALID + bias + relu -> flatT[k][b]
// ---------------------------------------------------------------------------
__global__ void conv_kernel(const float* __restrict__ cw,
                            const float* __restrict__ cb) {
    int idx = blockIdx.x * 256 + threadIdx.x;
    int b = idx & 31;
    int k = idx >> 5;
    int oc = k / 400;
    int pos = k - oc * 400;
    int oh = pos / 20;
    int ow = pos - oh * 20;
    float acc = cb[oc];
    const float* wp = cw + oc * 81;
#pragma unroll
    for (int r = 0; r < 9; ++r) {
#pragma unroll
        for (int cc = 0; cc < 9; ++cc) {
            acc = fmaf(g_xT[((oh + r) * 28 + ow + cc) * 32 + b], wp[r * 9 + cc], acc);
        }
    }
    g_flatT[(size_t)k * 32 + b] = fmaxf(acc, 0.f);
}

// ---------------------------------------------------------------------------
// 1b) act hi/lo split with smem transpose (coalesced both sides)
//     tile: 64 k x 32 b per block; 1600 blocks
// ---------------------------------------------------------------------------
__global__ void actcvt_kernel() {
    __shared__ float s[64][33];
    const int k0 = blockIdx.x * 64;
    const int t = threadIdx.x;
    const int r0 = t >> 5;                   // 0..7
    const int b = t & 31;
#pragma unroll
    for (int i = 0; i < 8; ++i)
        s[r0 + 8 * i][b] = g_flatT[(size_t)(k0 + r0 + 8 * i) * 32 + b];
    __syncthreads();
    const int bp = t >> 3;                   // 0..31
    const int cg = (t & 7) * 8;              // k offset within tile
    __nv_bfloat16 h8[8], l8[8];
#pragma unroll
    for (int u = 0; u < 8; ++u) {
        float f = s[cg + u][bp];
        __nv_bfloat16 h = __float2bfloat16_rn(f);
        h8[u] = h;
        l8[u] = __float2bfloat16_rn(f - __bfloat162float(h));
    }
    *(uint4*)&g_actH[(size_t)bp * FC_K + k0 + cg] = *(uint4*)h8;
    *(uint4*)&g_actL[(size_t)bp * FC_K + k0 + cg] = *(uint4*)l8;
}

// ---------------------------------------------------------------------------
// 2) FC via mma.sync bf16 hi/lo: Cpart[sk][m][b] = sum_k W[m][k]*act[b][k]
//    Block 256 = 8 warps, BM=256 (m32/warp), N=32 (4 n8), BK=16.
//    3-stage cp.async ring; end-of-iter wait_group 1 keeps the next chunk
//    in flight across the barrier (DRAM never drains).
// ---------------------------------------------------------------------------
__global__ void __launch_bounds__(256, 2)
fc_hmma_kernel(const float* __restrict__ fcw) {
    __shared__ __align__(16) float    wS[3][256 * WST];   // 72 KB
    __shared__ __align__(16) uint32_t bHs[3][32 * BST];   // 4.5 KB
    __shared__ __align__(16) uint32_t bLs[3][32 * BST];   // 4.5 KB

    const int t = threadIdx.x;
    const int mbase = blockIdx.x * 256;
    const long long kbase = (long long)blockIdx.y * FC_KSEG;

    // ---- cp.async geometry ----
    // weights: 1024 16B transfers/chunk; thread: row=t>>2 (+64j), kq=t&3
    const int wrow = t >> 2;                 // 0..63
    const int wkq = t & 3;                   // 16B group in the 64B chunk-row
    const float* wsrc = fcw + (size_t)(mbase + wrow) * FC_K + kbase + wkq * 4;
    const size_t wjstr = (size_t)64 * FC_K;
    // acts: 128 transfers/chunk; t<64 -> H, 64<=t<128 -> L
    const int an = (t & 63) >> 1;            // 0..31
    const int akq = t & 1;
    const __nv_bfloat16* asrc =
        ((t & 64) ? g_actL : g_actH) + (size_t)an * FC_K + kbase + akq * 8;

    const uint32_t wbase = smem_u32(&wS[0][0]);
    const uint32_t abase = ((t & 64) ? smem_u32(&bLs[0][0])
                                     : smem_u32(&bHs[0][0]));
    const uint32_t woffB = (uint32_t)(wrow * WST + wkq * 4) * 4;
    const uint32_t aoffB = (uint32_t)(an * BST + akq * 4) * 4;

#define FC_ISSUE(C, D)                                                       \
    {                                                                        \
        const float* p = wsrc + (size_t)(C) * 16;                            \
        const uint32_t wd = wbase + (uint32_t)(D) * 24576u + woffB;          \
        _Pragma("unroll")                                                    \
        for (int j = 0; j < 4; ++j)                                          \
            cp16(wd + j * (64 * WST * 4), p + j * wjstr);                    \
        if (t < 128)                                                         \
            cp16(abase + (uint32_t)(D) * 1536u + aoffB,                      \
                 asrc + (size_t)(C) * 16);                                   \
        cp_commit();                                                         \
    }

    // ---- compute geometry ----
    const int w = t >> 5;                    // warp: rows w*32 .. w*32+31
    const int lane = t & 31;
    const int gr = lane >> 2;                // 0..7
    const int gc = lane & 3;                 // 0..3

    float acc[2][4][4];
#pragma unroll
    for (int mt = 0; mt < 2; ++mt)
#pragma unroll
        for (int j = 0; j < 4; ++j)
#pragma unroll
            for (int q = 0; q < 4; ++q) acc[mt][j][q] = 0.f;

#define FC_COMPUTE(D)                                                        \
    {                                                                        \
        const float* wp_ = (const float*)((const char*)&wS[0][0] +           \
                                          (size_t)(D) * 24576u);             \
        const uint32_t* bhp = &bHs[0][0] + (size_t)(D) * 384u;               \
        const uint32_t* blp = &bLs[0][0] + (size_t)(D) * 384u;               \
        uint32_t bh[4][2], bl[4][2];                                         \
        _Pragma("unroll")                                                    \
        for (int j = 0; j < 4; ++j) {                                        \
            const int nb = (j * 8 + gr) * BST + gc;                          \
            bh[j][0] = bhp[nb]; bh[j][1] = bhp[nb + 4];                      \
            bl[j][0] = blp[nb]; bl[j][1] = blp[nb + 4];                      \
        }                                                                    \
        _Pragma("unroll")                                                    \
        for (int mt = 0; mt < 2; ++mt) {                                     \
            const int rb = (w * 32 + mt * 16 + gr) * WST + 2 * gc;           \
            float2 f0 = *(const float2*)&wp_[rb];                            \
            float2 f1 = *(const float2*)&wp_[rb + 8 * WST];                  \
            float2 f2 = *(const float2*)&wp_[rb + 8];                        \
            float2 f3 = *(const float2*)&wp_[rb + 8 * WST + 8];              \
            uint32_t ah0, ah1, ah2, ah3, al0, al1, al2, al3;                 \
            split_f2(f0, ah0, al0); split_f2(f1, ah1, al1);                  \
            split_f2(f2, ah2, al2); split_f2(f3, ah3, al3);                  \
            _Pragma("unroll")                                                \
            for (int j = 0; j < 4; ++j) {                                    \
                mma16816(acc[mt][j], ah0, ah1, ah2, ah3, bh[j][0], bh[j][1]);\
                mma16816(acc[mt][j], ah0, ah1, ah2, ah3, bl[j][0], bl[j][1]);\
                mma16816(acc[mt][j], al0, al1, al2, al3, bh[j][0], bh[j][1]);\
            }                                                                \
        }                                                                    \
    }

    // ---- prologue: fill two stages ----
    FC_ISSUE(0, 0)
    FC_ISSUE(1, 1)
    cp_wait1();                  // chunk 0 arrived; chunk 1 in flight
    __syncthreads();

    int buf = 0, ib = 2;
#pragma unroll 1
    for (int c = 0; c < FC_NCH; ++c) {
        const bool more2 = (c + 2) < FC_NCH;
        if (more2) FC_ISSUE(c + 2, ib)
        FC_COMPUTE(buf)
        if (more2) cp_wait1();                    // c+1 done, c+2 in flight
        else if (c + 1 < FC_NCH) cp_wait0();      // tail: ensure c+1 done
        __syncthreads();
        if (++buf == 3) buf = 0;
        if (++ib == 3) ib = 0;
    }

    // ---- epilogue: fragments -> g_Cpart ----
#pragma unroll
    for (int mt = 0; mt < 2; ++mt) {
        const int m0 = mbase + w * 32 + mt * 16 + gr;
#pragma unroll
        for (int j = 0; j < 4; ++j) {
            const int n0 = j * 8 + gc * 2;
            float* d0 = g_Cpart + ((size_t)blockIdx.y * FC_M + m0) * 32 + n0;
            float* d1 = d0 + (size_t)8 * 32;
            *(float2*)d0 = make_float2(acc[mt][j][0], acc[mt][j][1]);
            *(float2*)d1 = make_float2(acc[mt][j][2], acc[mt][j][3]);
        }
    }
#undef FC_ISSUE
#undef FC_COMPUTE
}

// ---------------------------------------------------------------------------
// 3) reduce split-K + bias + squash -> primary caps output + capsT scratch
// ---------------------------------------------------------------------------
__global__ void caps_kernel(const float* __restrict__ fcb,
                            float* __restrict__ out) {
    int idx = blockIdx.x * 256 + threadIdx.x;   // 36864
    int b = idx & 31;
    int cap = idx >> 5;
    float pc[8];
    float n2 = 0.f;
#pragma unroll
    for (int d = 0; d < 8; ++d) {
        int m = cap * 8 + d;
        float v = fcb[m];
#pragma unroll
        for (int s = 0; s < FC_SPLITK; ++s)
            v += g_Cpart[((size_t)s * FC_M + m) * 32 + b];
        pc[d] = v;
        n2 += v * v;
    }
    float scale = n2 / (1.f + n2);
    float inv = 1.f / sqrtf(n2);
#pragma unroll
    for (int d = 0; d < 8; ++d) {
        float o = scale * (pc[d] * inv + 1e-8f);
        out[OFF_PRIM + (size_t)b * 9216 + cap * 8 + d] = o;
        g_capsT[(cap * 8 + d) * 32 + b] = o;
    }
}

// ---------------------------------------------------------------------------
// 4) u_hat[b,n,p,d] = sum_i W[0,n,p,d,i] * caps[b,p,i] -> g_uhatT[n][p][d][b]
// ---------------------------------------------------------------------------
__global__ void uhat_kernel(const float* __restrict__ W) {
    int idx = blockIdx.x * 256 + threadIdx.x;   // 368640
    int b = idx & 31;
    int r = idx >> 5;                            // n*1152 + p
    int p = r % 1152;
    float caps[8];
#pragma unroll
    for (int i = 0; i < 8; ++i) caps[i] = g_capsT[(p * 8 + i) * 32 + b];
    const float* Wp = W + (size_t)r * 128;       // warp-uniform broadcast
    float* up = g_uhatT + (size_t)r * 512 + b;
#pragma unroll
    for (int d = 0; d < 16; ++d) {
        float a = 0.f;
#pragma unroll
        for (int i = 0; i < 8; ++i) a = fmaf(Wp[d * 8 + i], caps[i], a);
        up[d * 32] = a;
    }
}

// ---------------------------------------------------------------------------
// 5a) partial s sums over p-chunks of 32: spart[n][ch][d][b]
// ---------------------------------------------------------------------------
__global__ void rout_sv_kernel(int uniformC) {
    int n = blockIdx.x / 36;
    int ch = blockIdx.x - n * 36;
    int t = threadIdx.x;                         // 512 = 16 d * 32 b
    int b = t & 31;
    int d = t >> 5;
    int rbase = n * 1152 + ch * 32;
    float a = 0.f;
#pragma unroll 8
    for (int pp = 0; pp < 32; ++pp) {
        size_t r = rbase + pp;
        float c = uniformC ? 0.1f : g_cT[r * 32 + b];
        a = fmaf(c, g_uhatT[(r * 16 + d) * 32 + b], a);
    }
    g_spart[(((size_t)n * 36 + ch) * 16 + d) * 32 + b] = a;
}

// 5b) reduce partials + squash -> v (and digit caps output when final)
__global__ void rout_squash_kernel(int final_, float* __restrict__ out) {
    int t = threadIdx.x;                         // 320
    int b = t & 31;
    int n = t >> 5;
    float s[16];
    float n2 = 0.f;
#pragma unroll
    for (int d = 0; d < 16; ++d) {
        float a = 0.f;
        for (int ch = 0; ch < 36; ++ch)
            a += g_spart[(((size_t)n * 36 + ch) * 16 + d) * 32 + b];
        s[d] = a;
        n2 += a * a;
    }
    float scale = n2 / (1.f + n2);
    float inv = 1.f / sqrtf(n2);
#pragma unroll
    for (int d = 0; d < 16; ++d) {
        float v = scale * (s[d] * inv + 1e-8f);
        g_v[(n * 32 + b) * 16 + d] = v;
        if (final_) out[OFF_DIGIT + (size_t)b * 160 + n * 16 + d] = v;
    }
}

// 5c) b += sum_d u_hat * v   (first iteration: b = uv, since b starts at 0)
__global__ void rout_update_kernel(int first) {
    int idx = blockIdx.x * 256 + threadIdx.x;   // 368640
    int b = idx & 31;
    int r = idx >> 5;
    int n = r / 1152;
    const float* up = g_uhatT + (size_t)r * 512 + b;
    const float* vp = g_v + ((size_t)n * 32 + b) * 16;
    float a = 0.f;
#pragma unroll
    for (int d = 0; d < 16; ++d) a = fmaf(up[d * 32], vp[d], a);
    size_t o = (size_t)r * 32 + b;
    g_bT[o] = (first ? 0.f : g_bT[o]) + a;
}

// 5d) c = softmax over n of b; optionally emit final c and b to output
__global__ void softmax_kernel(int write_out, float* __restrict__ out) {
    int idx = blockIdx.x * 256 + threadIdx.x;   // 36864
    int b = idx & 31;
    int p = idx >> 5;
    float bv[10];
    float m = -1e30f;
#pragma unroll
    for (int n = 0; n < 10; ++n) {
        bv[n] = g_bT[((size_t)n * 1152 + p) * 32 + b];
        m = fmaxf(m, bv[n]);
    }
    float e[10];
    float sum = 0.f;
#pragma unroll
    for (int n = 0; n < 10; ++n) {
        e[n] = expf(bv[n] - m);
        sum += e[n];
    }
    float invs = 1.f / sum;
#pragma unroll
    for (int n = 0; n < 10; ++n) {
        float c = e[n] * invs;
        g_cT[((size_t)n * 1152 + p) * 32 + b] = c;
        if (write_out) {
            out[OFF_C + ((size_t)b * 10 + n) * 1152 + p] = c;
            out[OFF_B + ((size_t)b * 10 + n) * 1152 + p] = bv[n];
        }
    }
}

// ---------------------------------------------------------------------------
// 6) logits = ||digit||, argmax (first max), masked -> g_masked[i][b]
// ---------------------------------------------------------------------------
__global__ void logits_kernel(float* __restrict__ out) {
    int b = threadIdx.x;                         // 32
    float dg[160];
    for (int i = 0; i < 160; ++i) dg[i] = out[OFF_DIGIT + (size_t)b * 160 + i];
    float best = -1.f;
    int am = 0;
    for (int n = 0; n < 10; ++n) {
        float n2 = 0.f;
        for (int d = 0; d < 16; ++d) {
            float v = dg[n * 16 + d];
            n2 += v * v;
        }
        float lg = sqrtf(n2);
        out[OFF_LOGITS + b * 10 + n] = lg;
        if (lg > best) { best = lg; am = n; }
    }
    for (int n = 0; n < 10; ++n)
        for (int d = 0; d < 16; ++d)
            g_masked[(n * 16 + d) * 32 + b] = (n == am) ? dg[n * 16 + d] : 0.f;
}

// ---------------------------------------------------------------------------
// 7) decoder MLP
// ---------------------------------------------------------------------------
__global__ void dec1_kernel(const float* __restrict__ Wt,
                            const float* __restrict__ bias) {
    int idx = blockIdx.x * 256 + threadIdx.x;   // 512*32
    int b = idx & 31, o = idx >> 5;
    const float* w = Wt + (size_t)o * 160;
    float a0 = 0.f, a1 = 0.f, a2 = 0.f, a3 = 0.f;
#pragma unroll 4
    for (int i = 0; i < 160; i += 4) {
        a0 = fmaf(w[i],     g_masked[(i)     * 32 + b], a0);
        a1 = fmaf(w[i + 1], g_masked[(i + 1) * 32 + b], a1);
        a2 = fmaf(w[i + 2], g_masked[(i + 2) * 32 + b], a2);
        a3 = fmaf(w[i + 3], g_masked[(i + 3) * 32 + b], a3);
    }
    g_d1[o * 32 + b] = fmaxf(bias[o] + ((a0 + a1) + (a2 + a3)), 0.f);
}

__global__ void dec2_kernel(const float* __restrict__ Wt,
                            const float* __restrict__ bias) {
    int idx = blockIdx.x * 256 + threadIdx.x;   // 1024*32
    int b = idx & 31, o = idx >> 5;
    const float* w = Wt + (size_t)o * 512;
    float a0 = 0.f, a1 = 0.f, a2 = 0.f, a3 = 0.f;
#pragma unroll 4
    for (int i = 0; i < 512; i += 4) {
        a0 = fmaf(w[i],     g_d1[(i)     * 32 + b], a0);
        a1 = fmaf(w[i + 1], g_d1[(i + 1) * 32 + b], a1);
        a2 = fmaf(w[i + 2], g_d1[(i + 2) * 32 + b], a2);
        a3 = fmaf(w[i + 3], g_d1[(i + 3) * 32 + b], a3);
    }
    g_d2[o * 32 + b] = fmaxf(bias[o] + ((a0 + a1) + (a2 + a3)), 0.f);
}

__global__ void dec3_kernel(const float* __restrict__ Wt,
                            const float* __restrict__ bias,
                            float* __restrict__ out) {
    int idx = blockIdx.x * 256 + threadIdx.x;   // 784*32
    int b = idx & 31, o = idx >> 5;
    const float* w = Wt + (size_t)o * 1024;
    float a0 = 0.f, a1 = 0.f, a2 = 0.f, a3 = 0.f;
#pragma unroll 4
    for (int i = 0; i < 1024; i += 4) {
        a0 = fmaf(w[i],     g_d2[(i)     * 32 + b], a0);
        a1 = fmaf(w[i + 1], g_d2[(i + 1) * 32 + b], a1);
        a2 = fmaf(w[i + 2], g_d2[(i + 2) * 32 + b], a2);
        a3 = fmaf(w[i + 3], g_d2[(i + 3) * 32 + b], a3);
    }
    float x = bias[o] + ((a0 + a1) + (a2 + a3));
    out[OFF_RECON + (size_t)b * 784 + o] = 1.f / (1.f + expf(-x));
}

// ---------------------------------------------------------------------------
// Resolve inputs by (unique) element count — order-independent binding.
// ---------------------------------------------------------------------------
static const float* by_size(void* const* d_in, const int* s, int n, int want) {
    for (int i = 0; i < n; ++i)
        if (s[i] == want) return (const float*)d_in[i];
    return nullptr;
}

extern "C" void kernel_launch(void* const* d_in, const int* in_sizes, int n_in,
                              void* d_out, int out_size) {
    const float* x   = by_size(d_in, in_sizes, n_in, 32 * 784);        // 25088
    const float* cw  = by_size(d_in, in_sizes, n_in, 256 * 81);        // 20736
    const float* cb  = by_size(d_in, in_sizes, n_in, 256);
    const float* fcw = by_size(d_in, in_sizes, n_in, 943718400);       // 9216*102400
    const float* fcb = by_size(d_in, in_sizes, n_in, 9216);
    const float* W   = by_size(d_in, in_sizes, n_in, 1474560);         // 10*1152*16*8
    const float* d1w = by_size(d_in, in_sizes, n_in, 512 * 160);       // 81920
    const float* d1b = by_size(d_in, in_sizes, n_in, 512);
    const float* d2w = by_size(d_in, in_sizes, n_in, 1024 * 512);      // 524288
    const float* d2b = by_size(d_in, in_sizes, n_in, 1024);
    const float* d3w = by_size(d_in, in_sizes, n_in, 784 * 1024);      // 802816
    const float* d3b = by_size(d_in, in_sizes, n_in, 784);
    float* out = (float*)d_out;

    xT_kernel<<<98, 256>>>(x);                           // launch 1
    conv_kernel<<<12800, 256>>>(cw, cb);                 // launch 2
    actcvt_kernel<<<1600, 256>>>();                      // launch 3
    fc_hmma_kernel<<<dim3(36, 8), 256>>>(fcw);           // launch 4 <- ncu slot
    caps_kernel<<<144, 256>>>(fcb, out);
    uhat_kernel<<<1440, 256>>>(W);

    // routing iteration 0 (c = softmax(0) = 0.1 uniform)
    rout_sv_kernel<<<360, 512>>>(1);
    rout_squash_kernel<<<1, 320>>>(0, out);
    rout_update_kernel<<<1440, 256>>>(1);
    // routing iteration 1
    softmax_kernel<<<144, 256>>>(0, out);
    rout_sv_kernel<<<360, 512>>>(0);
    rout_squash_kernel<<<1, 320>>>(0, out);
    rout_update_kernel<<<1440, 256>>>(0);
    // final pass (emit c, b, digit caps)
    softmax_kernel<<<144, 256>>>(1, out);
    rout_sv_kernel<<<360, 512>>>(0);
    rout_squash_kernel<<<1, 320>>>(1, out);

    logits_kernel<<<1, 32>>>(out);
    dec1_kernel<<<64, 256>>>(d1w, d1b);
    dec2_kernel<<<128, 256>>>(d2w, d2b);
    dec3_kernel<<<98, 256>>>(d3w, d3b, out);
}